// round 1
// baseline (speedup 1.0000x reference)
#include <cuda_runtime.h>
#include <math.h>

#define Bb 4
#define Tt 1024
#define Vv 50257
#define Ee 1024
#define Hh 16
#define Ll 8
#define Dd 64
#define BT (Bb*Tt)

// ---------------- device scratch (static, allocation-free) ----------------
__device__ float g_x [BT*Ee];
__device__ float g_h [BT*Ee];
__device__ float g_q [BT*Ee];
__device__ float g_k [BT*Ee];
__device__ float g_v [BT*Ee];
__device__ float g_o [BT*Ee];
__device__ float g_ff[BT*Ee];
__device__ float g_sc[67108864ull];          // [B*H, T, T] attention scores/probs (256 MB)
__device__ float g_rowloss[BT];
__device__ float g_logits_scratch[205852672ull]; // fallback if d_out doesn't hold logits

// ---------------- reductions ----------------
__device__ __forceinline__ float warpSum(float v){
  #pragma unroll
  for (int o = 16; o > 0; o >>= 1) v += __shfl_down_sync(0xffffffffu, v, o);
  return v;
}
__device__ __forceinline__ float warpMax(float v){
  #pragma unroll
  for (int o = 16; o > 0; o >>= 1) v = fmaxf(v, __shfl_down_sync(0xffffffffu, v, o));
  return v;
}
template<int OP>  // 0 = sum, 1 = max
__device__ __forceinline__ float blockReduce(float v){
  __shared__ float sh[33];
  int lane = threadIdx.x & 31, wid = threadIdx.x >> 5;
  v = OP ? warpMax(v) : warpSum(v);
  __syncthreads();                 // protect shared reuse across back-to-back calls
  if (lane == 0) sh[wid] = v;
  __syncthreads();
  int nw = blockDim.x >> 5;
  if (wid == 0){
    float u = (lane < nw) ? sh[lane] : (OP ? -INFINITY : 0.0f);
    u = OP ? warpMax(u) : warpSum(u);
    if (lane == 0) sh[32] = u;
  }
  __syncthreads();
  return sh[32];
}

// ---------------- embedding: x = tok_emb[idx] * pos_emb[t] ----------------
__global__ void embed_kernel(const int* __restrict__ idx,
                             const float* __restrict__ tok,
                             const float* __restrict__ pos){
  int i  = blockIdx.x * 256 + threadIdx.x;     // over BT * (E/4)
  int e4 = i & (Ee/4 - 1);
  int bt = i >> 8;                              // E/4 = 256
  int t  = bt & (Tt - 1);
  int token = idx[bt];
  float4 tv = ((const float4*)(tok + (size_t)token * Ee))[e4];
  float4 pv = ((const float4*)(pos + (size_t)t     * Ee))[e4];
  ((float4*)(g_x + (size_t)bt * Ee))[e4] =
      make_float4(tv.x*pv.x, tv.y*pv.y, tv.z*pv.z, tv.w*pv.w);
}

// ---------------- layernorm (one row per block, 256 threads) ----------------
__global__ void ln_kernel(const float* __restrict__ in, float* __restrict__ out,
                          const float* __restrict__ w, const float* __restrict__ b){
  int row = blockIdx.x;
  float4 v = ((const float4*)(in + (size_t)row * Ee))[threadIdx.x];
  float mu = blockReduce<0>(v.x + v.y + v.z + v.w) * (1.0f / Ee);
  float dx = v.x - mu, dy = v.y - mu, dz = v.z - mu, dw = v.w - mu;
  float var = blockReduce<0>(dx*dx + dy*dy + dz*dz + dw*dw) * (1.0f / Ee);
  float rs = rsqrtf(var + 1e-5f);
  float4 wv = ((const float4*)w)[threadIdx.x];
  float4 bv = ((const float4*)b)[threadIdx.x];
  ((float4*)(out + (size_t)row * Ee))[threadIdx.x] =
      make_float4(dx*rs*wv.x + bv.x, dy*rs*wv.y + bv.y,
                  dz*rs*wv.z + bv.z, dw*rs*wv.w + bv.w);
}

// ---------------- generic SGEMM: C = act(A@B + bias) (+ resid) ----------------
// 128x128 tile, BK=16, 256 threads, 8x8 per thread.
template<bool RELU, bool RESID>
__global__ __launch_bounds__(256)
void sgemm(const float* __restrict__ A, const float* __restrict__ Bm,
           const float* __restrict__ bias, const float* __restrict__ resid,
           float* __restrict__ C, int M, int N, int K){
  __shared__ float As[16][128];   // transposed: [k][m]
  __shared__ float Bs[16][128];   // [k][n]
  int bm = blockIdx.y, bn = blockIdx.x;
  int tid = threadIdx.x;
  int tx = tid & 15, ty = tid >> 4;
  int row0 = bm * 128, col0 = bn * 128;
  bool n_vec = ((N & 3) == 0);
  float acc[8][8] = {};

  for (int kt = 0; kt < K; kt += 16){
    #pragma unroll
    for (int l = 0; l < 2; l++){
      int f = tid + l * 256;              // 0..511
      int r = f >> 2, c4 = (f & 3) << 2;  // A tile 128 x 16
      float4 av = *(const float4*)(A + (size_t)(row0 + r) * K + kt + c4);
      As[c4+0][r] = av.x; As[c4+1][r] = av.y; As[c4+2][r] = av.z; As[c4+3][r] = av.w;
    }
    #pragma unroll
    for (int l = 0; l < 2; l++){
      int f = tid + l * 256;
      int r = f >> 5, c4 = (f & 31) << 2; // B tile 16 x 128
      int gc = col0 + c4;
      float4 bv2;
      if (n_vec && gc + 3 < N){
        bv2 = *(const float4*)(Bm + (size_t)(kt + r) * N + gc);
      } else {
        const float* bp = Bm + (size_t)(kt + r) * N;
        bv2.x = (gc     < N) ? bp[gc    ] : 0.0f;
        bv2.y = (gc + 1 < N) ? bp[gc + 1] : 0.0f;
        bv2.z = (gc + 2 < N) ? bp[gc + 2] : 0.0f;
        bv2.w = (gc + 3 < N) ? bp[gc + 3] : 0.0f;
      }
      *(float4*)(&Bs[r][c4]) = bv2;
    }
    __syncthreads();
    #pragma unroll
    for (int kk = 0; kk < 16; kk++){
      float4 a0 = *(const float4*)(&As[kk][ty * 4]);
      float4 a1 = *(const float4*)(&As[kk][ty * 4 + 64]);
      float4 b0 = *(const float4*)(&Bs[kk][tx * 4]);
      float4 b1 = *(const float4*)(&Bs[kk][tx * 4 + 64]);
      float a[8] = {a0.x,a0.y,a0.z,a0.w, a1.x,a1.y,a1.z,a1.w};
      float bb[8] = {b0.x,b0.y,b0.z,b0.w, b1.x,b1.y,b1.z,b1.w};
      #pragma unroll
      for (int i = 0; i < 8; i++)
        #pragma unroll
        for (int j = 0; j < 8; j++)
          acc[i][j] += a[i] * bb[j];
    }
    __syncthreads();
  }

  #pragma unroll
  for (int i = 0; i < 8; i++){
    int r = row0 + ty * 4 + (i & 3) + (i >> 2) * 64;
    #pragma unroll
    for (int j = 0; j < 8; j++){
      int c = col0 + tx * 4 + (j & 3) + (j >> 2) * 64;
      if (c < N){
        float vv = acc[i][j];
        if (bias)  vv += bias[c];
        if (RELU)  vv = fmaxf(vv, 0.0f);
        if (RESID) vv += resid[(size_t)r * N + c];
        C[(size_t)r * N + c] = vv;
      }
    }
  }
}

// ---------------- attention scores: S = scale * Q Kᵀ with causal mask ----------------
// tile 64(i) x 64(j), K=D=64 full. 256 threads, 4x4 per thread.
__global__ __launch_bounds__(256)
void attn_scores(const float* __restrict__ q, const float* __restrict__ k){
  int jb = blockIdx.x, ib = blockIdx.y, bh = blockIdx.z;
  if (jb > ib) return;                          // fully masked block; softmax zeroes tail
  int b = bh >> 4, h = bh & 15;
  const float* qh = q + (size_t)b * Tt * Ee + h * Dd;
  const float* kh = k + (size_t)b * Tt * Ee + h * Dd;
  __shared__ float QsT[64][64];   // [d][i]
  __shared__ float KsT[64][64];   // [d][j]
  int tid = threadIdx.x, tx = tid & 15, ty = tid >> 4;
  #pragma unroll
  for (int l = 0; l < 4; l++){
    int f = tid + l * 256;                      // 0..1023
    int r = f >> 4, c4 = (f & 15) << 2;
    float4 v4 = *(const float4*)(qh + (size_t)(ib * 64 + r) * Ee + c4);
    QsT[c4+0][r] = v4.x; QsT[c4+1][r] = v4.y; QsT[c4+2][r] = v4.z; QsT[c4+3][r] = v4.w;
    float4 w4 = *(const float4*)(kh + (size_t)(jb * 64 + r) * Ee + c4);
    KsT[c4+0][r] = w4.x; KsT[c4+1][r] = w4.y; KsT[c4+2][r] = w4.z; KsT[c4+3][r] = w4.w;
  }
  __syncthreads();
  float acc[4][4] = {};
  #pragma unroll 8
  for (int kk = 0; kk < 64; kk++){
    float4 a4 = *(const float4*)(&QsT[kk][ty * 4]);
    float4 b4 = *(const float4*)(&KsT[kk][tx * 4]);
    float a[4] = {a4.x,a4.y,a4.z,a4.w};
    float bb[4] = {b4.x,b4.y,b4.z,b4.w};
    #pragma unroll
    for (int i = 0; i < 4; i++)
      #pragma unroll
      for (int j = 0; j < 4; j++)
        acc[i][j] += a[i] * bb[j];
  }
  const float scale = 0.03125f;                 // E^{-1/2} = 1/32
  #pragma unroll
  for (int i = 0; i < 4; i++){
    int gi = ib * 64 + ty * 4 + i;
    #pragma unroll
    for (int j = 0; j < 4; j++){
      int gj = jb * 64 + tx * 4 + j;
      float s = (gj <= gi) ? acc[i][j] * scale : -INFINITY;
      g_sc[((size_t)bh * Tt + gi) * Tt + gj] = s;
    }
  }
}

// ---------------- causal softmax (in place over g_sc) ----------------
__global__ void softmax_kernel(){
  int row = blockIdx.x;            // bh*T + i
  int i = row & (Tt - 1);
  float* s = g_sc + (size_t)row * Tt;
  int n = i + 1;
  float m = -INFINITY;
  for (int j = threadIdx.x; j < n; j += 256) m = fmaxf(m, s[j]);
  m = blockReduce<1>(m);
  float sum = 0.0f;
  for (int j = threadIdx.x; j < n; j += 256) sum += __expf(s[j] - m);
  sum = blockReduce<0>(sum);
  float inv = 1.0f / sum;
  for (int j = threadIdx.x; j < Tt; j += 256)
    s[j] = (j < n) ? __expf(s[j] - m) * inv : 0.0f;
}

// ---------------- attention output: O = A V (causally truncated K loop) ----------------
__global__ __launch_bounds__(256)
void attn_out(const float* __restrict__ v){
  int ib = blockIdx.y, bh = blockIdx.z;
  int b = bh >> 4, h = bh & 15;
  const float* vh  = v + (size_t)b * Tt * Ee + h * Dd;
  const float* att = g_sc + (size_t)bh * Tt * Tt;
  __shared__ float AsT[64][64];   // [j][i]
  __shared__ float Vs [64][64];   // [j][d]
  int tid = threadIdx.x, tx = tid & 15, ty = tid >> 4;
  float acc[4][4] = {};
  int kend = ib * 64 + 64;
  for (int kt = 0; kt < kend; kt += 64){
    #pragma unroll
    for (int l = 0; l < 4; l++){
      int f = tid + l * 256;
      int r = f >> 4, c4 = (f & 15) << 2;
      float4 a4 = *(const float4*)(att + (size_t)(ib * 64 + r) * Tt + kt + c4);
      AsT[c4+0][r] = a4.x; AsT[c4+1][r] = a4.y; AsT[c4+2][r] = a4.z; AsT[c4+3][r] = a4.w;
      float4 v4 = *(const float4*)(vh + (size_t)(kt + r) * Ee + c4);
      *(float4*)(&Vs[r][c4]) = v4;
    }
    __syncthreads();
    #pragma unroll 8
    for (int kk = 0; kk < 64; kk++){
      float4 a4 = *(const float4*)(&AsT[kk][ty * 4]);
      float4 b4 = *(const float4*)(&Vs[kk][tx * 4]);
      float a[4] = {a4.x,a4.y,a4.z,a4.w};
      float bb[4] = {b4.x,b4.y,b4.z,b4.w};
      #pragma unroll
      for (int i = 0; i < 4; i++)
        #pragma unroll
        for (int j = 0; j < 4; j++)
          acc[i][j] += a[i] * bb[j];
    }
    __syncthreads();
  }
  #pragma unroll
  for (int i = 0; i < 4; i++){
    int gi = ib * 64 + ty * 4 + i;
    float4 o4 = make_float4(acc[i][0], acc[i][1], acc[i][2], acc[i][3]);
    *(float4*)(g_o + (size_t)(b * Tt + gi) * Ee + h * Dd + tx * 4) = o4;
  }
}

// ---------------- loss ----------------
__global__ void loss_row(const float* __restrict__ logits, const int* __restrict__ tgt){
  int r = blockIdx.x;
  const float* lp = logits + (size_t)r * Vv;
  float m = -INFINITY;
  for (int c = threadIdx.x; c < Vv; c += 256) m = fmaxf(m, lp[c]);
  m = blockReduce<1>(m);
  float s = 0.0f;
  for (int c = threadIdx.x; c < Vv; c += 256) s += __expf(lp[c] - m);
  s = blockReduce<0>(s);
  if (threadIdx.x == 0) g_rowloss[r] = -(lp[tgt[r]] - m - logf(s));
}
__global__ void loss_final(float* __restrict__ out){
  float s = 0.0f;
  for (int i = threadIdx.x; i < BT; i += 256) s += g_rowloss[i];
  s = blockReduce<0>(s);
  if (threadIdx.x == 0) out[0] = s / (float)BT;
}

// ---------------- launch ----------------
extern "C" void kernel_launch(void* const* d_in, const int* in_sizes, int n_in,
                              void* d_out, int out_size){
  const int*   idx     = (const int*)  d_in[0];
  const int*   targets = (const int*)  d_in[1];
  const float* tok     = (const float*)d_in[2];
  const float* pos     = (const float*)d_in[3];
  const float* ln1w    = (const float*)d_in[4];
  const float* ln1b    = (const float*)d_in[5];
  const float* Wq      = (const float*)d_in[6];
  const float* Wk      = (const float*)d_in[7];
  const float* Wv      = (const float*)d_in[8];
  const float* projw   = (const float*)d_in[9];
  const float* projb   = (const float*)d_in[10];
  const float* ln2w    = (const float*)d_in[11];
  const float* ln2b    = (const float*)d_in[12];
  const float* fw1     = (const float*)d_in[13];
  const float* fb1     = (const float*)d_in[14];
  const float* fw2     = (const float*)d_in[15];
  const float* fb2     = (const float*)d_in[16];
  const float* lnfw    = (const float*)d_in[17];
  const float* lnfb    = (const float*)d_in[18];
  const float* lmw     = (const float*)d_in[19];
  const float* lmb     = (const float*)d_in[20];

  float *x, *h, *q, *k, *v, *o, *ff, *scratch;
  cudaGetSymbolAddress((void**)&x,  g_x);
  cudaGetSymbolAddress((void**)&h,  g_h);
  cudaGetSymbolAddress((void**)&q,  g_q);
  cudaGetSymbolAddress((void**)&k,  g_k);
  cudaGetSymbolAddress((void**)&v,  g_v);
  cudaGetSymbolAddress((void**)&o,  g_o);
  cudaGetSymbolAddress((void**)&ff, g_ff);
  cudaGetSymbolAddress((void**)&scratch, g_logits_scratch);

  const long long bt_v = (long long)BT * Vv;
  float* logits = ((long long)out_size >= bt_v) ? (float*)d_out : scratch;

  embed_kernel<<<BT * Ee / 4 / 256, 256>>>(idx, tok, pos);

  dim3 g128(Ee / 128, BT / 128);   // (8, 32)
  for (int l = 0; l < Ll; l++){
    size_t wo = (size_t)l * Ee * Ee, bo = (size_t)l * Ee;
    ln_kernel<<<BT, 256>>>(x, h, ln1w + bo, ln1b + bo);
    sgemm<false,false><<<g128, 256>>>(h, Wq + wo, nullptr, nullptr, q, BT, Ee, Ee);
    sgemm<false,false><<<g128, 256>>>(h, Wk + wo, nullptr, nullptr, k, BT, Ee, Ee);
    sgemm<false,false><<<g128, 256>>>(h, Wv + wo, nullptr, nullptr, v, BT, Ee, Ee);
    attn_scores<<<dim3(Tt/64, Tt/64, Bb*Hh), 256>>>(q, k);
    softmax_kernel<<<Bb * Hh * Tt, 256>>>();
    attn_out<<<dim3(1, Tt/64, Bb*Hh), 256>>>(v);
    sgemm<false,true ><<<g128, 256>>>(o,  projw + wo, projb + bo, x, x, BT, Ee, Ee);
    ln_kernel<<<BT, 256>>>(x, h, ln2w + bo, ln2b + bo);
    sgemm<true ,false><<<g128, 256>>>(h,  fw1 + wo, fb1 + bo, nullptr, ff, BT, Ee, Ee);
    sgemm<false,true ><<<g128, 256>>>(ff, fw2 + wo, fb2 + bo, x, x, BT, Ee, Ee);
  }

  ln_kernel<<<BT, 256>>>(x, h, lnfw, lnfb);
  sgemm<false,false><<<dim3((Vv + 127) / 128, BT / 128), 256>>>(
      h, lmw, lmb, nullptr, logits, BT, Vv, Ee);

  if ((long long)out_size != bt_v){
    loss_row<<<BT, 256>>>(logits, targets);
    float* lossptr = ((long long)out_size > bt_v) ? ((float*)d_out) + bt_v
                                                  : (float*)d_out;
    loss_final<<<1, 256>>>(lossptr);
  }
}

// round 3
// speedup vs baseline: 2.0427x; 2.0427x over previous
#include <cuda_runtime.h>
#include <math.h>
#include <stdint.h>

#define Bb 4
#define Tt 1024
#define Vv 50257
#define Ee 1024
#define Hh 16
#define Ll 8
#define Dd 64
#define BT (Bb*Tt)

// ---------------- device scratch (static, allocation-free) ----------------
__device__ float g_x [BT*Ee];
__device__ float g_h [BT*Ee];
__device__ float g_q [BT*Ee];
__device__ float g_k [BT*Ee];
__device__ float g_v [BT*Ee];
__device__ float g_o [BT*Ee];
__device__ float g_ff[BT*Ee];
__device__ float g_sc[67108864ull];          // [B*H, T, T] scores/probs (256 MB)
__device__ float g_rowloss[BT];
__device__ float g_logits_scratch[205852672ull];

// ---------------- helpers ----------------
__device__ __forceinline__ uint32_t f2tf(float f){
  uint32_t u; asm("cvt.rna.tf32.f32 %0, %1;" : "=r"(u) : "f"(f)); return u;
}
__device__ __forceinline__ void mma8(float* c, const uint32_t* a, const uint32_t* b){
  asm volatile("mma.sync.aligned.m16n8k8.row.col.f32.tf32.tf32.f32 "
    "{%0,%1,%2,%3}, {%4,%5,%6,%7}, {%8,%9}, {%0,%1,%2,%3};"
    : "+f"(c[0]), "+f"(c[1]), "+f"(c[2]), "+f"(c[3])
    : "r"(a[0]), "r"(a[1]), "r"(a[2]), "r"(a[3]), "r"(b[0]), "r"(b[1]));
}

__device__ __forceinline__ float warpSum(float v){
  #pragma unroll
  for (int o = 16; o > 0; o >>= 1) v += __shfl_down_sync(0xffffffffu, v, o);
  return v;
}
__device__ __forceinline__ float warpMax(float v){
  #pragma unroll
  for (int o = 16; o > 0; o >>= 1) v = fmaxf(v, __shfl_down_sync(0xffffffffu, v, o));
  return v;
}
template<int OP>  // 0 = sum, 1 = max
__device__ __forceinline__ float blockReduce(float v){
  __shared__ float sh[33];
  int lane = threadIdx.x & 31, wid = threadIdx.x >> 5;
  v = OP ? warpMax(v) : warpSum(v);
  __syncthreads();
  if (lane == 0) sh[wid] = v;
  __syncthreads();
  int nw = blockDim.x >> 5;
  if (wid == 0){
    float u = (lane < nw) ? sh[lane] : (OP ? -INFINITY : 0.0f);
    u = OP ? warpMax(u) : warpSum(u);
    if (lane == 0) sh[32] = u;
  }
  __syncthreads();
  return sh[32];
}

// ---------------- embedding ----------------
__global__ void embed_kernel(const int* __restrict__ idx,
                             const float* __restrict__ tok,
                             const float* __restrict__ pos){
  int i  = blockIdx.x * 256 + threadIdx.x;
  int e4 = i & (Ee/4 - 1);
  int bt = i >> 8;
  int t  = bt & (Tt - 1);
  int token = idx[bt];
  float4 tv = ((const float4*)(tok + (size_t)token * Ee))[e4];
  float4 pv = ((const float4*)(pos + (size_t)t     * Ee))[e4];
  ((float4*)(g_x + (size_t)bt * Ee))[e4] =
      make_float4(tv.x*pv.x, tv.y*pv.y, tv.z*pv.z, tv.w*pv.w);
}

// ---------------- layernorm ----------------
__global__ void ln_kernel(const float* __restrict__ in, float* __restrict__ out,
                          const float* __restrict__ w, const float* __restrict__ b){
  int row = blockIdx.x;
  float4 v = ((const float4*)(in + (size_t)row * Ee))[threadIdx.x];
  float mu = blockReduce<0>(v.x + v.y + v.z + v.w) * (1.0f / Ee);
  float dx = v.x - mu, dy = v.y - mu, dz = v.z - mu, dw = v.w - mu;
  float var = blockReduce<0>(dx*dx + dy*dy + dz*dz + dw*dw) * (1.0f / Ee);
  float rs = rsqrtf(var + 1e-5f);
  float4 wv = ((const float4*)w)[threadIdx.x];
  float4 bv = ((const float4*)b)[threadIdx.x];
  ((float4*)(out + (size_t)row * Ee))[threadIdx.x] =
      make_float4(dx*rs*wv.x + bv.x, dy*rs*wv.y + bv.y,
                  dz*rs*wv.z + bv.z, dw*rs*wv.w + bv.w);
}

// ---------------- tf32 tensor-core SGEMM ----------------
// C[M,N] = act(A[M,K] @ B[K,N] + bias) (+resid). BM=BN=128, BK=32.
// 256 threads = 8 warps as 2(M) x 4(N); warp tile 64x32; mma m16n8k8.
#define APITCH 36   // == 4 (mod 32): a-frag reads conflict-free
#define BPITCH 136  // == 8 (mod 32): b-frag reads conflict-free
template<bool RELU, bool RESID>
__global__ __launch_bounds__(256, 2)
void sgemm_tc(const float* __restrict__ A, const float* __restrict__ Bm,
              const float* __restrict__ bias, const float* __restrict__ resid,
              float* __restrict__ C, int M, int N, int K){
  __shared__ uint32_t As[128 * APITCH];   // [m][k]
  __shared__ uint32_t Bs[32 * BPITCH];    // [k][n]
  int tid = threadIdx.x;
  int lane = tid & 31, warp = tid >> 5;
  int wm = warp >> 2, wn = warp & 3;
  int qk = lane & 3, qm = lane >> 2;
  int row0 = blockIdx.y * 128, col0 = blockIdx.x * 128;
  bool n_vec = ((N & 3) == 0);
  bool n_even = ((N & 1) == 0);     // float2 stores legal only when row stride is 8B-aligned
  float acc[4][4][4] = {};

  for (int kt = 0; kt < K; kt += 32){
    #pragma unroll
    for (int l = 0; l < 4; l++){
      int f = tid + l * 256;              // A tile 128m x 32k
      int m = f >> 3, k4 = (f & 7) << 2;
      float4 av = *(const float4*)(A + (size_t)(row0 + m) * K + kt + k4);
      uint32_t* d = &As[m * APITCH + k4];
      d[0] = f2tf(av.x); d[1] = f2tf(av.y); d[2] = f2tf(av.z); d[3] = f2tf(av.w);
    }
    #pragma unroll
    for (int l = 0; l < 4; l++){
      int f = tid + l * 256;              // B tile 32k x 128n
      int kk = f >> 5, n4 = (f & 31) << 2;
      int gc = col0 + n4;
      float4 bv;
      if (n_vec && gc + 3 < N){
        bv = *(const float4*)(Bm + (size_t)(kt + kk) * N + gc);
      } else {
        const float* bp = Bm + (size_t)(kt + kk) * N;
        bv.x = (gc     < N) ? bp[gc    ] : 0.0f;
        bv.y = (gc + 1 < N) ? bp[gc + 1] : 0.0f;
        bv.z = (gc + 2 < N) ? bp[gc + 2] : 0.0f;
        bv.w = (gc + 3 < N) ? bp[gc + 3] : 0.0f;
      }
      uint32_t* d = &Bs[kk * BPITCH + n4];
      d[0] = f2tf(bv.x); d[1] = f2tf(bv.y); d[2] = f2tf(bv.z); d[3] = f2tf(bv.w);
    }
    __syncthreads();
    #pragma unroll
    for (int ks = 0; ks < 4; ks++){
      int k0 = ks * 8;
      uint32_t af[4][4], bf[4][2];
      #pragma unroll
      for (int mi = 0; mi < 4; mi++){
        int mb = wm * 64 + mi * 16 + qm;
        af[mi][0] = As[(mb    ) * APITCH + k0 + qk];
        af[mi][1] = As[(mb + 8) * APITCH + k0 + qk];
        af[mi][2] = As[(mb    ) * APITCH + k0 + 4 + qk];
        af[mi][3] = As[(mb + 8) * APITCH + k0 + 4 + qk];
      }
      #pragma unroll
      for (int ni = 0; ni < 4; ni++){
        int nb = wn * 32 + ni * 8 + qm;
        bf[ni][0] = Bs[(k0     + qk) * BPITCH + nb];
        bf[ni][1] = Bs[(k0 + 4 + qk) * BPITCH + nb];
      }
      #pragma unroll
      for (int mi = 0; mi < 4; mi++)
        #pragma unroll
        for (int ni = 0; ni < 4; ni++)
          mma8(acc[mi][ni], af[mi], bf[ni]);
    }
    __syncthreads();
  }

  #pragma unroll
  for (int mi = 0; mi < 4; mi++){
    int r = row0 + wm * 64 + mi * 16 + qm;
    #pragma unroll
    for (int ni = 0; ni < 4; ni++){
      int c = col0 + wn * 32 + ni * 8 + qk * 2;
      #pragma unroll
      for (int half = 0; half < 2; half++){
        int rr = r + half * 8;
        float v0 = acc[mi][ni][half * 2 + 0];
        float v1 = acc[mi][ni][half * 2 + 1];
        if (bias){ if (c < N) v0 += bias[c]; if (c+1 < N) v1 += bias[c+1]; }
        if (RELU){ v0 = fmaxf(v0, 0.0f); v1 = fmaxf(v1, 0.0f); }
        if (RESID){
          const float* rp = resid + (size_t)rr * N;
          if (c < N) v0 += rp[c];
          if (c + 1 < N) v1 += rp[c + 1];
        }
        float* cp = C + (size_t)rr * N;
        if (n_even && c + 1 < N){
          *(float2*)(cp + c) = make_float2(v0, v1);   // 8B-aligned: N even, c even
        } else {
          if (c     < N) cp[c    ] = v0;
          if (c + 1 < N) cp[c + 1] = v1;
        }
      }
    }
  }
}

// ---------------- attention scores: S = scale * Q K^T, causal ----------------
// tile 64(i) x 64(j), k=D=64. 8 warps: 2(M)x4(N), warp tile 32x16.
#define QPITCH 68   // == 4 (mod 32)
__global__ __launch_bounds__(256)
void attn_scores(const float* __restrict__ q, const float* __restrict__ k){
  int jb = blockIdx.x, ib = blockIdx.y, bh = blockIdx.z;
  if (jb > ib) return;
  int b = bh >> 4, h = bh & 15;
  const float* qh = q + (size_t)b * Tt * Ee + h * Dd;
  const float* kh = k + (size_t)b * Tt * Ee + h * Dd;
  __shared__ uint32_t Qs[64 * QPITCH];  // [i][d]
  __shared__ uint32_t Ks[64 * QPITCH];  // [j][d]
  int tid = threadIdx.x;
  int lane = tid & 31, warp = tid >> 5;
  int wm = warp >> 2, wn = warp & 3;
  int qk = lane & 3, qm = lane >> 2;
  #pragma unroll
  for (int l = 0; l < 4; l++){
    int f = tid + l * 256;
    int r = f >> 4, c4 = (f & 15) << 2;
    float4 v4 = *(const float4*)(qh + (size_t)(ib * 64 + r) * Ee + c4);
    uint32_t* d = &Qs[r * QPITCH + c4];
    d[0] = f2tf(v4.x); d[1] = f2tf(v4.y); d[2] = f2tf(v4.z); d[3] = f2tf(v4.w);
    float4 w4 = *(const float4*)(kh + (size_t)(jb * 64 + r) * Ee + c4);
    uint32_t* e = &Ks[r * QPITCH + c4];
    e[0] = f2tf(w4.x); e[1] = f2tf(w4.y); e[2] = f2tf(w4.z); e[3] = f2tf(w4.w);
  }
  __syncthreads();
  float acc[2][2][4] = {};
  #pragma unroll
  for (int ks = 0; ks < 8; ks++){
    int k0 = ks * 8;
    uint32_t af[2][4], bf[2][2];
    #pragma unroll
    for (int mi = 0; mi < 2; mi++){
      int mb = wm * 32 + mi * 16 + qm;
      af[mi][0] = Qs[(mb    ) * QPITCH + k0 + qk];
      af[mi][1] = Qs[(mb + 8) * QPITCH + k0 + qk];
      af[mi][2] = Qs[(mb    ) * QPITCH + k0 + 4 + qk];
      af[mi][3] = Qs[(mb + 8) * QPITCH + k0 + 4 + qk];
    }
    #pragma unroll
    for (int ni = 0; ni < 2; ni++){
      int nb = wn * 16 + ni * 8 + qm;
      bf[ni][0] = Ks[nb * QPITCH + k0 + qk];
      bf[ni][1] = Ks[nb * QPITCH + k0 + 4 + qk];
    }
    #pragma unroll
    for (int mi = 0; mi < 2; mi++)
      #pragma unroll
      for (int ni = 0; ni < 2; ni++)
        mma8(acc[mi][ni], af[mi], bf[ni]);
  }
  const float scale = 0.03125f;   // E^{-1/2}
  #pragma unroll
  for (int mi = 0; mi < 2; mi++){
    #pragma unroll
    for (int ni = 0; ni < 2; ni++){
      int gj = jb * 64 + wn * 16 + ni * 8 + qk * 2;
      #pragma unroll
      for (int half = 0; half < 2; half++){
        int gi = ib * 64 + wm * 32 + mi * 16 + qm + half * 8;
        float s0 = (gj     <= gi) ? acc[mi][ni][half*2+0] * scale : -INFINITY;
        float s1 = (gj + 1 <= gi) ? acc[mi][ni][half*2+1] * scale : -INFINITY;
        *(float2*)(g_sc + ((size_t)bh * Tt + gi) * Tt + gj) = make_float2(s0, s1);
      }
    }
  }
}

// ---------------- causal softmax ----------------
__global__ void softmax_kernel(){
  int row = blockIdx.x;
  int i = row & (Tt - 1);
  float* s = g_sc + (size_t)row * Tt;
  int n = i + 1;
  float m = -INFINITY;
  for (int j = threadIdx.x; j < n; j += 256) m = fmaxf(m, s[j]);
  m = blockReduce<1>(m);
  float sum = 0.0f;
  for (int j = threadIdx.x; j < n; j += 256) sum += __expf(s[j] - m);
  sum = blockReduce<0>(sum);
  float inv = 1.0f / sum;
  for (int j = threadIdx.x; j < Tt; j += 256)
    s[j] = (j < n) ? __expf(s[j] - m) * inv : 0.0f;
}

// ---------------- attention output: O = A V ----------------
#define VPITCH 72   // == 8 (mod 32)
__global__ __launch_bounds__(256)
void attn_out(const float* __restrict__ v){
  int ib = blockIdx.y, bh = blockIdx.z;
  int b = bh >> 4, h = bh & 15;
  const float* vh  = v + (size_t)b * Tt * Ee + h * Dd;
  const float* att = g_sc + (size_t)bh * Tt * Tt;
  __shared__ uint32_t As2[64 * QPITCH];  // [i][j]
  __shared__ uint32_t Vs [64 * VPITCH];  // [j][d]
  int tid = threadIdx.x;
  int lane = tid & 31, warp = tid >> 5;
  int wm = warp >> 2, wn = warp & 3;
  int qk = lane & 3, qm = lane >> 2;
  float acc[2][2][4] = {};
  int kend = ib * 64 + 64;
  for (int kt = 0; kt < kend; kt += 64){
    #pragma unroll
    for (int l = 0; l < 4; l++){
      int f = tid + l * 256;
      int r = f >> 4, c4 = (f & 15) << 2;
      float4 a4 = *(const float4*)(att + (size_t)(ib * 64 + r) * Tt + kt + c4);
      uint32_t* d = &As2[r * QPITCH + c4];
      d[0] = f2tf(a4.x); d[1] = f2tf(a4.y); d[2] = f2tf(a4.z); d[3] = f2tf(a4.w);
      float4 v4 = *(const float4*)(vh + (size_t)(kt + r) * Ee + c4);
      uint32_t* e = &Vs[r * VPITCH + c4];
      e[0] = f2tf(v4.x); e[1] = f2tf(v4.y); e[2] = f2tf(v4.z); e[3] = f2tf(v4.w);
    }
    __syncthreads();
    #pragma unroll
    for (int ks = 0; ks < 8; ks++){
      int k0 = ks * 8;
      uint32_t af[2][4], bf[2][2];
      #pragma unroll
      for (int mi = 0; mi < 2; mi++){
        int mb = wm * 32 + mi * 16 + qm;
        af[mi][0] = As2[(mb    ) * QPITCH + k0 + qk];
        af[mi][1] = As2[(mb + 8) * QPITCH + k0 + qk];
        af[mi][2] = As2[(mb    ) * QPITCH + k0 + 4 + qk];
        af[mi][3] = As2[(mb + 8) * QPITCH + k0 + 4 + qk];
      }
      #pragma unroll
      for (int ni = 0; ni < 2; ni++){
        int nb = wn * 16 + ni * 8 + qm;
        bf[ni][0] = Vs[(k0     + qk) * VPITCH + nb];
        bf[ni][1] = Vs[(k0 + 4 + qk) * VPITCH + nb];
      }
      #pragma unroll
      for (int mi = 0; mi < 2; mi++)
        #pragma unroll
        for (int ni = 0; ni < 2; ni++)
          mma8(acc[mi][ni], af[mi], bf[ni]);
    }
    __syncthreads();
  }
  #pragma unroll
  for (int mi = 0; mi < 2; mi++){
    #pragma unroll
    for (int ni = 0; ni < 2; ni++){
      int col = wn * 16 + ni * 8 + qk * 2;
      #pragma unroll
      for (int half = 0; half < 2; half++){
        int gi = ib * 64 + wm * 32 + mi * 16 + qm + half * 8;
        *(float2*)(g_o + (size_t)(b * Tt + gi) * Ee + h * Dd + col) =
            make_float2(acc[mi][ni][half*2+0], acc[mi][ni][half*2+1]);
      }
    }
  }
}

// ---------------- loss ----------------
__global__ void loss_row(const float* __restrict__ logits, const int* __restrict__ tgt){
  int r = blockIdx.x;
  const float* lp = logits + (size_t)r * Vv;
  float m = -INFINITY;
  for (int c = threadIdx.x; c < Vv; c += 256) m = fmaxf(m, lp[c]);
  m = blockReduce<1>(m);
  float s = 0.0f;
  for (int c = threadIdx.x; c < Vv; c += 256) s += __expf(lp[c] - m);
  s = blockReduce<0>(s);
  if (threadIdx.x == 0) g_rowloss[r] = -(lp[tgt[r]] - m - logf(s));
}
__global__ void loss_final(float* __restrict__ out){
  float s = 0.0f;
  for (int i = threadIdx.x; i < BT; i += 256) s += g_rowloss[i];
  s = blockReduce<0>(s);
  if (threadIdx.x == 0) out[0] = s / (float)BT;
}

// ---------------- launch ----------------
extern "C" void kernel_launch(void* const* d_in, const int* in_sizes, int n_in,
                              void* d_out, int out_size){
  const int*   idx     = (const int*)  d_in[0];
  const int*   targets = (const int*)  d_in[1];
  const float* tok     = (const float*)d_in[2];
  const float* pos     = (const float*)d_in[3];
  const float* ln1w    = (const float*)d_in[4];
  const float* ln1b    = (const float*)d_in[5];
  const float* Wq      = (const float*)d_in[6];
  const float* Wk      = (const float*)d_in[7];
  const float* Wv      = (const float*)d_in[8];
  const float* projw   = (const float*)d_in[9];
  const float* projb   = (const float*)d_in[10];
  const float* ln2w    = (const float*)d_in[11];
  const float* ln2b    = (const float*)d_in[12];
  const float* fw1     = (const float*)d_in[13];
  const float* fb1     = (const float*)d_in[14];
  const float* fw2     = (const float*)d_in[15];
  const float* fb2     = (const float*)d_in[16];
  const float* lnfw    = (const float*)d_in[17];
  const float* lnfb    = (const float*)d_in[18];
  const float* lmw     = (const float*)d_in[19];
  const float* lmb     = (const float*)d_in[20];

  float *x, *h, *q, *k, *v, *o, *ff, *scratch;
  cudaGetSymbolAddress((void**)&x,  g_x);
  cudaGetSymbolAddress((void**)&h,  g_h);
  cudaGetSymbolAddress((void**)&q,  g_q);
  cudaGetSymbolAddress((void**)&k,  g_k);
  cudaGetSymbolAddress((void**)&v,  g_v);
  cudaGetSymbolAddress((void**)&o,  g_o);
  cudaGetSymbolAddress((void**)&ff, g_ff);
  cudaGetSymbolAddress((void**)&scratch, g_logits_scratch);

  const long long bt_v = (long long)BT * Vv;
  float* logits = ((long long)out_size >= bt_v) ? (float*)d_out : scratch;

  embed_kernel<<<BT * Ee / 4 / 256, 256>>>(idx, tok, pos);

  dim3 g128(Ee / 128, BT / 128);   // (8, 32)
  for (int l = 0; l < Ll; l++){
    size_t wo = (size_t)l * Ee * Ee, bo = (size_t)l * Ee;
    ln_kernel<<<BT, 256>>>(x, h, ln1w + bo, ln1b + bo);
    sgemm_tc<false,false><<<g128, 256>>>(h, Wq + wo, nullptr, nullptr, q, BT, Ee, Ee);
    sgemm_tc<false,false><<<g128, 256>>>(h, Wk + wo, nullptr, nullptr, k, BT, Ee, Ee);
    sgemm_tc<false,false><<<g128, 256>>>(h, Wv + wo, nullptr, nullptr, v, BT, Ee, Ee);
    attn_scores<<<dim3(Tt/64, Tt/64, Bb*Hh), 256>>>(q, k);
    softmax_kernel<<<Bb * Hh * Tt, 256>>>();
    attn_out<<<dim3(1, Tt/64, Bb*Hh), 256>>>(v);
    sgemm_tc<false,true ><<<g128, 256>>>(o,  projw + wo, projb + bo, x, x, BT, Ee, Ee);
    ln_kernel<<<BT, 256>>>(x, h, ln2w + bo, ln2b + bo);
    sgemm_tc<true ,false><<<g128, 256>>>(h,  fw1 + wo, fb1 + bo, nullptr, ff, BT, Ee, Ee);
    sgemm_tc<false,true ><<<g128, 256>>>(ff, fw2 + wo, fb2 + bo, x, x, BT, Ee, Ee);
  }

  ln_kernel<<<BT, 256>>>(x, h, lnfw, lnfb);
  sgemm_tc<false,false><<<dim3((Vv + 127) / 128, BT / 128), 256>>>(
      h, lmw, lmb, nullptr, logits, BT, Vv, Ee);

  if ((long long)out_size != bt_v){
    loss_row<<<BT, 256>>>(logits, targets);
    float* lossptr = ((long long)out_size > bt_v) ? ((float*)d_out) + bt_v
                                                  : (float*)d_out;
    loss_final<<<1, 256>>>(lossptr);
  }
}

// round 5
// speedup vs baseline: 3.7106x; 1.8165x over previous
#include <cuda_runtime.h>
#include <math.h>
#include <stdint.h>

#define Bb 4
#define Tt 1024
#define Vv 50257
#define Ee 1024
#define Hh 16
#define Ll 8
#define Dd 64
#define BT (Bb*Tt)
#define NPAD 50304   // Vv padded to multiple of 128

// ---------------- device scratch (static, allocation-free) ----------------
__device__ float g_x [BT*Ee];
__device__ float g_h [BT*Ee];
__device__ float g_q [BT*Ee];
__device__ float g_k [BT*Ee];
__device__ float g_v [BT*Ee];
__device__ float g_o [BT*Ee];
__device__ float g_ff[BT*Ee];
__device__ float g_rowloss[BT];
__device__ float g_lmw_pad[(size_t)Ee * NPAD];        // 206 MB aligned LM weight
__device__ float g_logits_scratch[205852672ull];      // fallback logits buffer

// ---------------- helpers ----------------
__device__ __forceinline__ uint32_t f2tf(float f){
  uint32_t u; asm("cvt.rna.tf32.f32 %0, %1;" : "=r"(u) : "f"(f)); return u;
}
__device__ __forceinline__ void mma8(float* c, const uint32_t* a, const uint32_t* b){
  asm volatile("mma.sync.aligned.m16n8k8.row.col.f32.tf32.tf32.f32 "
    "{%0,%1,%2,%3}, {%4,%5,%6,%7}, {%8,%9}, {%0,%1,%2,%3};"
    : "+f"(c[0]), "+f"(c[1]), "+f"(c[2]), "+f"(c[3])
    : "r"(a[0]), "r"(a[1]), "r"(a[2]), "r"(a[3]), "r"(b[0]), "r"(b[1]));
}
__device__ __forceinline__ void cp16(void* smem_ptr, const void* g){
  uint32_t s = (uint32_t)__cvta_generic_to_shared(smem_ptr);
  asm volatile("cp.async.cg.shared.global [%0], [%1], 16;" :: "r"(s), "l"(g));
}
__device__ __forceinline__ void cp_commit(){ asm volatile("cp.async.commit_group;"); }
template<int N> __device__ __forceinline__ void cp_wait(){
  asm volatile("cp.async.wait_group %0;" :: "n"(N));
}

__device__ __forceinline__ float warpSum(float v){
  #pragma unroll
  for (int o = 16; o > 0; o >>= 1) v += __shfl_down_sync(0xffffffffu, v, o);
  return v;
}
__device__ __forceinline__ float warpMax(float v){
  #pragma unroll
  for (int o = 16; o > 0; o >>= 1) v = fmaxf(v, __shfl_down_sync(0xffffffffu, v, o));
  return v;
}
template<int OP>
__device__ __forceinline__ float blockReduce(float v){
  __shared__ float sh[33];
  int lane = threadIdx.x & 31, wid = threadIdx.x >> 5;
  v = OP ? warpMax(v) : warpSum(v);
  __syncthreads();
  if (lane == 0) sh[wid] = v;
  __syncthreads();
  int nw = blockDim.x >> 5;
  if (wid == 0){
    float u = (lane < nw) ? sh[lane] : (OP ? -INFINITY : 0.0f);
    u = OP ? warpMax(u) : warpSum(u);
    if (lane == 0) sh[32] = u;
  }
  __syncthreads();
  return sh[32];
}

// ---------------- embedding ----------------
__global__ void embed_kernel(const int* __restrict__ idx,
                             const float* __restrict__ tok,
                             const float* __restrict__ pos){
  int i  = blockIdx.x * 256 + threadIdx.x;
  int e4 = i & (Ee/4 - 1);
  int bt = i >> 8;
  int t  = bt & (Tt - 1);
  int token = idx[bt];
  float4 tv = ((const float4*)(tok + (size_t)token * Ee))[e4];
  float4 pv = ((const float4*)(pos + (size_t)t     * Ee))[e4];
  ((float4*)(g_x + (size_t)bt * Ee))[e4] =
      make_float4(tv.x*pv.x, tv.y*pv.y, tv.z*pv.z, tv.w*pv.w);
}

// ---------------- layernorm ----------------
__global__ void ln_kernel(const float* __restrict__ in, float* __restrict__ out,
                          const float* __restrict__ w, const float* __restrict__ b){
  int row = blockIdx.x;
  float4 v = ((const float4*)(in + (size_t)row * Ee))[threadIdx.x];
  float mu = blockReduce<0>(v.x + v.y + v.z + v.w) * (1.0f / Ee);
  float dx = v.x - mu, dy = v.y - mu, dz = v.z - mu, dw = v.w - mu;
  float var = blockReduce<0>(dx*dx + dy*dy + dz*dz + dw*dw) * (1.0f / Ee);
  float rs = rsqrtf(var + 1e-5f);
  float4 wv = ((const float4*)w)[threadIdx.x];
  float4 bv = ((const float4*)b)[threadIdx.x];
  ((float4*)(out + (size_t)row * Ee))[threadIdx.x] =
      make_float4(dx*rs*wv.x + bv.x, dy*rs*wv.y + bv.y,
                  dz*rs*wv.z + bv.z, dw*rs*wv.w + bv.w);
}

// ---------------- LM weight repack: [K][Vv] -> [K][NPAD] zero-padded ----------------
__global__ void repack_lmw(const float* __restrict__ lmw){
  int i = blockIdx.x * 256 + threadIdx.x;   // over Ee * NPAD/4
  const int npad4 = NPAD / 4;
  int k  = i / npad4;
  int c4 = (i - k * npad4) * 4;
  const float* src = lmw + (size_t)k * Vv;
  float4 v;
  v.x = (c4     < Vv) ? src[c4    ] : 0.0f;
  v.y = (c4 + 1 < Vv) ? src[c4 + 1] : 0.0f;
  v.z = (c4 + 2 < Vv) ? src[c4 + 2] : 0.0f;
  v.w = (c4 + 3 < Vv) ? src[c4 + 3] : 0.0f;
  *(float4*)(g_lmw_pad + (size_t)k * NPAD + c4) = v;
}

// ---------------- tf32 tensor-core GEMM, 2-stage cp.async pipeline ----------------
// C[M,N] = act(A@B + bias)(+resid). BM=BN=128, BK=32. grid.x = M blocks (L2 reuse).
#define APITCH 36     // == 4 (mod 32)
#define BPITCH 136    // == 8 (mod 32)
#define ASZ (128*APITCH)           // 4608 floats
#define STAGEF (ASZ + 32*BPITCH)   // 8960 floats per stage
#define SGEMM_SMEM (2*STAGEF*4)    // 71680 bytes

template<bool RELU, bool RESID>
__global__ __launch_bounds__(256, 2)
void sgemm_tc(const float* __restrict__ A, const float* __restrict__ Bm,
              const float* __restrict__ bias, const float* __restrict__ resid,
              float* __restrict__ C, int M, int N, int K, int Nb){
  extern __shared__ __align__(16) float dsm[];
  int tid = threadIdx.x;
  int lane = tid & 31, warp = tid >> 5;
  int wm = warp >> 2, wn = warp & 3;
  int qk = lane & 3, qm = lane >> 2;
  int row0 = blockIdx.x * 128, col0 = blockIdx.y * 128;
  bool n_even = ((N & 1) == 0);
  float acc[4][4][4] = {};

  auto prefetch = [&](int kt, int s){
    float* As = dsm + s * STAGEF;
    float* Bs = As + ASZ;
    #pragma unroll
    for (int l = 0; l < 4; l++){
      int f = tid + l * 256;
      int m = f >> 3, k4 = (f & 7) << 2;
      cp16(As + m * APITCH + k4, A + (size_t)(row0 + m) * K + kt + k4);
    }
    #pragma unroll
    for (int l = 0; l < 4; l++){
      int f = tid + l * 256;
      int kk = f >> 5, n4 = (f & 31) << 2;
      cp16(Bs + kk * BPITCH + n4, Bm + (size_t)(kt + kk) * Nb + col0 + n4);
    }
  };

  int nk = K >> 5;
  prefetch(0, 0); cp_commit();
  for (int t = 0; t < nk; t++){
    if (t + 1 < nk){ prefetch((t + 1) << 5, (t + 1) & 1); cp_commit(); cp_wait<1>(); }
    else cp_wait<0>();
    __syncthreads();
    const float* As = dsm + (t & 1) * STAGEF;
    const float* Bs = As + ASZ;
    #pragma unroll
    for (int ks = 0; ks < 4; ks++){
      int k0 = ks * 8;
      uint32_t af[4][4], bf[4][2];
      #pragma unroll
      for (int mi = 0; mi < 4; mi++){
        int mb = wm * 64 + mi * 16 + qm;
        af[mi][0] = f2tf(As[(mb    ) * APITCH + k0 + qk]);
        af[mi][1] = f2tf(As[(mb + 8) * APITCH + k0 + qk]);
        af[mi][2] = f2tf(As[(mb    ) * APITCH + k0 + 4 + qk]);
        af[mi][3] = f2tf(As[(mb + 8) * APITCH + k0 + 4 + qk]);
      }
      #pragma unroll
      for (int ni = 0; ni < 4; ni++){
        int nb = wn * 32 + ni * 8 + qm;
        bf[ni][0] = f2tf(Bs[(k0     + qk) * BPITCH + nb]);
        bf[ni][1] = f2tf(Bs[(k0 + 4 + qk) * BPITCH + nb]);
      }
      #pragma unroll
      for (int mi = 0; mi < 4; mi++)
        #pragma unroll
        for (int ni = 0; ni < 4; ni++)
          mma8(acc[mi][ni], af[mi], bf[ni]);
    }
    __syncthreads();
  }

  #pragma unroll
  for (int mi = 0; mi < 4; mi++){
    int r = row0 + wm * 64 + mi * 16 + qm;
    #pragma unroll
    for (int ni = 0; ni < 4; ni++){
      int c = col0 + wn * 32 + ni * 8 + qk * 2;
      #pragma unroll
      for (int half = 0; half < 2; half++){
        int rr = r + half * 8;
        float v0 = acc[mi][ni][half * 2 + 0];
        float v1 = acc[mi][ni][half * 2 + 1];
        if (bias){ if (c < N) v0 += bias[c]; if (c + 1 < N) v1 += bias[c + 1]; }
        if (RELU){ v0 = fmaxf(v0, 0.0f); v1 = fmaxf(v1, 0.0f); }
        if (RESID){
          const float* rp = resid + (size_t)rr * N;
          if (c < N) v0 += rp[c];
          if (c + 1 < N) v1 += rp[c + 1];
        }
        float* cp = C + (size_t)rr * N;
        if (n_even && c + 1 < N){
          *(float2*)(cp + c) = make_float2(v0, v1);
        } else {
          if (c     < N) cp[c    ] = v0;
          if (c + 1 < N) cp[c + 1] = v1;
        }
      }
    }
  }
}

// ---------------- fused flash attention (causal) ----------------
// grid (T/64, B*H), 128 threads = 4 warps, each warp owns 16 query rows.
#define KPITCH 68
#define VPITCH 72
#define PPITCH 68
#define FLASH_SMEM ((64*KPITCH + 64*VPITCH + 64*PPITCH) * 4)   // 53248 B

__global__ __launch_bounds__(128)
void flash_attn(const float* __restrict__ q, const float* __restrict__ k,
                const float* __restrict__ v){
  extern __shared__ __align__(16) float fsm[];
  float*    Ks  = fsm;
  float*    Vs  = fsm + 64 * KPITCH;
  float*    Ps  = Vs  + 64 * VPITCH;
  uint32_t* KsU = (uint32_t*)Ks;
  uint32_t* VsU = (uint32_t*)Vs;
  uint32_t* PsU = (uint32_t*)Ps;

  int it = blockIdx.x, bh = blockIdx.y;
  int b = bh >> 4, hd = bh & 15;
  const float* qh = q + (size_t)b * Tt * Ee + hd * Dd;
  const float* kh = k + (size_t)b * Tt * Ee + hd * Dd;
  const float* vh = v + (size_t)b * Tt * Ee + hd * Dd;

  int tid = threadIdx.x;
  int lane = tid & 31, warp = tid >> 5;
  int qk = lane & 3, qm = lane >> 2;
  int r0 = warp * 16;

  // stage Q tile (64x64) through Ps, build per-warp A-frags (held in regs)
  #pragma unroll
  for (int l = 0; l < 8; l++){
    int f = tid + l * 128;
    int r = f >> 4, c4 = (f & 15) << 2;
    float4 qv = *(const float4*)(qh + (size_t)(it * 64 + r) * Ee + c4);
    *(float4*)(Ps + r * PPITCH + c4) = qv;
  }
  __syncthreads();
  uint32_t aq[8][4];
  #pragma unroll
  for (int ks = 0; ks < 8; ks++){
    aq[ks][0] = f2tf(Ps[(r0 + qm    ) * PPITCH + ks * 8 + qk]);
    aq[ks][1] = f2tf(Ps[(r0 + qm + 8) * PPITCH + ks * 8 + qk]);
    aq[ks][2] = f2tf(Ps[(r0 + qm    ) * PPITCH + ks * 8 + qk + 4]);
    aq[ks][3] = f2tf(Ps[(r0 + qm + 8) * PPITCH + ks * 8 + qk + 4]);
  }

  float oacc[8][4] = {};
  float mold[2] = {-INFINITY, -INFINITY};
  float lrun[2] = {0.0f, 0.0f};
  const float scale = 0.03125f;   // E^{-1/2}

  for (int jt = 0; jt <= it; jt++){
    __syncthreads();
    #pragma unroll
    for (int l = 0; l < 8; l++){
      int f = tid + l * 128;
      int r = f >> 4, c4 = (f & 15) << 2;
      float4 kv = *(const float4*)(kh + (size_t)(jt * 64 + r) * Ee + c4);
      uint32_t* kd = &KsU[r * KPITCH + c4];
      kd[0] = f2tf(kv.x); kd[1] = f2tf(kv.y); kd[2] = f2tf(kv.z); kd[3] = f2tf(kv.w);
      float4 vv = *(const float4*)(vh + (size_t)(jt * 64 + r) * Ee + c4);
      uint32_t* vd = &VsU[r * VPITCH + c4];
      vd[0] = f2tf(vv.x); vd[1] = f2tf(vv.y); vd[2] = f2tf(vv.z); vd[3] = f2tf(vv.w);
    }
    __syncthreads();

    // S = Q @ K^T for this warp's 16 rows x 64 cols
    float sacc[8][4] = {};
    #pragma unroll
    for (int ks = 0; ks < 8; ks++){
      #pragma unroll
      for (int ni = 0; ni < 8; ni++){
        uint32_t ub[2];
        ub[0] = KsU[(ni * 8 + qm) * KPITCH + ks * 8 + qk];
        ub[1] = KsU[(ni * 8 + qm) * KPITCH + ks * 8 + qk + 4];
        mma8(sacc[ni], aq[ks], ub);
      }
    }

    // scale + causal mask (diagonal tile only)
    bool diag = (jt == it);
    #pragma unroll
    for (int ni = 0; ni < 8; ni++)
      #pragma unroll
      for (int e = 0; e < 4; e++){
        float sv = sacc[ni][e] * scale;
        if (diag){
          int rr = r0 + qm + ((e >> 1) << 3);        // FIXED: include warp offset
          int cc = ni * 8 + (qk << 1) + (e & 1);
          if (cc > rr) sv = -INFINITY;
        }
        sacc[ni][e] = sv;
      }

    // online softmax per row-half; write P (tf32) to this warp's Ps region
    #pragma unroll
    for (int h = 0; h < 2; h++){
      float mr = -INFINITY;
      #pragma unroll
      for (int ni = 0; ni < 8; ni++)
        mr = fmaxf(mr, fmaxf(sacc[ni][h * 2], sacc[ni][h * 2 + 1]));
      mr = fmaxf(mr, __shfl_xor_sync(0xffffffffu, mr, 1));
      mr = fmaxf(mr, __shfl_xor_sync(0xffffffffu, mr, 2));
      float mn = fmaxf(mold[h], mr);
      float alpha = __expf(mold[h] - mn);
      mold[h] = mn;
      float ls = 0.0f;
      int prow = (r0 + qm + h * 8) * PPITCH;
      #pragma unroll
      for (int ni = 0; ni < 8; ni++){
        float p0 = __expf(sacc[ni][h * 2    ] - mn);
        float p1 = __expf(sacc[ni][h * 2 + 1] - mn);
        ls += p0 + p1;
        PsU[prow + ni * 8 + qk * 2    ] = f2tf(p0);
        PsU[prow + ni * 8 + qk * 2 + 1] = f2tf(p1);
        oacc[ni][h * 2    ] *= alpha;
        oacc[ni][h * 2 + 1] *= alpha;
      }
      ls += __shfl_xor_sync(0xffffffffu, ls, 1);
      ls += __shfl_xor_sync(0xffffffffu, ls, 2);
      lrun[h] = lrun[h] * alpha + ls;
    }
    __syncwarp();

    // O += P @ V
    #pragma unroll
    for (int ks = 0; ks < 8; ks++){
      uint32_t ua[4];
      ua[0] = PsU[(r0 + qm    ) * PPITCH + ks * 8 + qk];
      ua[1] = PsU[(r0 + qm + 8) * PPITCH + ks * 8 + qk];
      ua[2] = PsU[(r0 + qm    ) * PPITCH + ks * 8 + qk + 4];
      ua[3] = PsU[(r0 + qm + 8) * PPITCH + ks * 8 + qk + 4];
      #pragma unroll
      for (int ni = 0; ni < 8; ni++){
        uint32_t ub[2];
        ub[0] = VsU[(ks * 8 + qk    ) * VPITCH + ni * 8 + qm];
        ub[1] = VsU[(ks * 8 + qk + 4) * VPITCH + ni * 8 + qm];
        mma8(oacc[ni], ua, ub);
      }
    }
  }

  #pragma unroll
  for (int h = 0; h < 2; h++){
    float inv = 1.0f / lrun[h];
    int gi = it * 64 + r0 + qm + h * 8;
    float* op = g_o + (size_t)(b * Tt + gi) * Ee + hd * Dd;
    #pragma unroll
    for (int ni = 0; ni < 8; ni++)
      *(float2*)(op + ni * 8 + qk * 2) =
          make_float2(oacc[ni][h * 2] * inv, oacc[ni][h * 2 + 1] * inv);
  }
}

// ---------------- loss ----------------
__global__ void loss_row(const float* __restrict__ logits, const int* __restrict__ tgt){
  int r = blockIdx.x;
  const float* lp = logits + (size_t)r * Vv;
  float m = -INFINITY;
  for (int c = threadIdx.x; c < Vv; c += 256) m = fmaxf(m, lp[c]);
  m = blockReduce<1>(m);
  float s = 0.0f;
  for (int c = threadIdx.x; c < Vv; c += 256) s += __expf(lp[c] - m);
  s = blockReduce<0>(s);
  if (threadIdx.x == 0) g_rowloss[r] = -(lp[tgt[r]] - m - logf(s));
}
__global__ void loss_final(float* __restrict__ out){
  float s = 0.0f;
  for (int i = threadIdx.x; i < BT; i += 256) s += g_rowloss[i];
  s = blockReduce<0>(s);
  if (threadIdx.x == 0) out[0] = s / (float)BT;
}

// ---------------- launch ----------------
extern "C" void kernel_launch(void* const* d_in, const int* in_sizes, int n_in,
                              void* d_out, int out_size){
  const int*   idx     = (const int*)  d_in[0];
  const int*   targets = (const int*)  d_in[1];
  const float* tok     = (const float*)d_in[2];
  const float* pos     = (const float*)d_in[3];
  const float* ln1w    = (const float*)d_in[4];
  const float* ln1b    = (const float*)d_in[5];
  const float* Wq      = (const float*)d_in[6];
  const float* Wk      = (const float*)d_in[7];
  const float* Wv      = (const float*)d_in[8];
  const float* projw   = (const float*)d_in[9];
  const float* projb   = (const float*)d_in[10];
  const float* ln2w    = (const float*)d_in[11];
  const float* ln2b    = (const float*)d_in[12];
  const float* fw1     = (const float*)d_in[13];
  const float* fb1     = (const float*)d_in[14];
  const float* fw2     = (const float*)d_in[15];
  const float* fb2     = (const float*)d_in[16];
  const float* lnfw    = (const float*)d_in[17];
  const float* lnfb    = (const float*)d_in[18];
  const float* lmw     = (const float*)d_in[19];
  const float* lmb     = (const float*)d_in[20];

  float *x, *h, *q, *k, *v, *o, *ff, *lmwpad, *scratch;
  cudaGetSymbolAddress((void**)&x,  g_x);
  cudaGetSymbolAddress((void**)&h,  g_h);
  cudaGetSymbolAddress((void**)&q,  g_q);
  cudaGetSymbolAddress((void**)&k,  g_k);
  cudaGetSymbolAddress((void**)&v,  g_v);
  cudaGetSymbolAddress((void**)&o,  g_o);
  cudaGetSymbolAddress((void**)&ff, g_ff);
  cudaGetSymbolAddress((void**)&lmwpad, g_lmw_pad);
  cudaGetSymbolAddress((void**)&scratch, g_logits_scratch);

  cudaFuncSetAttribute(sgemm_tc<false,false>, cudaFuncAttributeMaxDynamicSharedMemorySize, SGEMM_SMEM);
  cudaFuncSetAttribute(sgemm_tc<false,true >, cudaFuncAttributeMaxDynamicSharedMemorySize, SGEMM_SMEM);
  cudaFuncSetAttribute(sgemm_tc<true ,false>, cudaFuncAttributeMaxDynamicSharedMemorySize, SGEMM_SMEM);
  cudaFuncSetAttribute(flash_attn, cudaFuncAttributeMaxDynamicSharedMemorySize, FLASH_SMEM);

  const long long bt_v = (long long)BT * Vv;
  float* logits = ((long long)out_size >= bt_v) ? (float*)d_out : scratch;

  embed_kernel<<<BT * Ee / 4 / 256, 256>>>(idx, tok, pos);
  repack_lmw<<<Ee * (NPAD/4) / 256, 256>>>(lmw);

  dim3 gEE(BT / 128, Ee / 128);      // x = M blocks, y = N blocks
  dim3 gAttn(Tt / 64, Bb * Hh);
  for (int l = 0; l < Ll; l++){
    size_t wo = (size_t)l * Ee * Ee, bo = (size_t)l * Ee;
    ln_kernel<<<BT, 256>>>(x, h, ln1w + bo, ln1b + bo);
    sgemm_tc<false,false><<<gEE, 256, SGEMM_SMEM>>>(h, Wq + wo, nullptr, nullptr, q, BT, Ee, Ee, Ee);
    sgemm_tc<false,false><<<gEE, 256, SGEMM_SMEM>>>(h, Wk + wo, nullptr, nullptr, k, BT, Ee, Ee, Ee);
    sgemm_tc<false,false><<<gEE, 256, SGEMM_SMEM>>>(h, Wv + wo, nullptr, nullptr, v, BT, Ee, Ee, Ee);
    flash_attn<<<gAttn, 128, FLASH_SMEM>>>(q, k, v);
    sgemm_tc<false,true ><<<gEE, 256, SGEMM_SMEM>>>(o,  projw + wo, projb + bo, x, x, BT, Ee, Ee, Ee);
    ln_kernel<<<BT, 256>>>(x, h, ln2w + bo, ln2b + bo);
    sgemm_tc<true ,false><<<gEE, 256, SGEMM_SMEM>>>(h,  fw1 + wo, fb1 + bo, nullptr, ff, BT, Ee, Ee, Ee);
    sgemm_tc<false,true ><<<gEE, 256, SGEMM_SMEM>>>(ff, fw2 + wo, fb2 + bo, x, x, BT, Ee, Ee, Ee);
  }

  ln_kernel<<<BT, 256>>>(x, h, lnfw, lnfb);
  sgemm_tc<false,false><<<dim3(BT / 128, NPAD / 128), 256, SGEMM_SMEM>>>(
      h, lmwpad, lmb, nullptr, logits, BT, Vv, Ee, NPAD);

  if ((long long)out_size != bt_v){
    loss_row<<<BT, 256>>>(logits, targets);
    float* lossptr = ((long long)out_size > bt_v) ? ((float*)d_out) + bt_v
                                                  : (float*)d_out;
    loss_final<<<1, 256>>>(lossptr);
  }
}

// round 6
// speedup vs baseline: 5.2608x; 1.4178x over previous
#include <cuda_runtime.h>
#include <cuda_fp16.h>
#include <math.h>
#include <stdint.h>

#define Bb 4
#define Tt 1024
#define Vv 50257
#define Ee 1024
#define Hh 16
#define Ll 8
#define Dd 64
#define BT (Bb*Tt)
#define NPAD 50304   // Vv padded to multiple of 128

// ---------------- device scratch (static, allocation-free) ----------------
__device__ float  g_x [BT*Ee];                       // fp32 residual stream
__device__ __half g_hh[BT*Ee];                       // LN output (GEMM A)
__device__ __half g_qh[BT*Ee];
__device__ __half g_kh[BT*Ee];
__device__ __half g_vh[BT*Ee];
__device__ __half g_oh[BT*Ee];
__device__ __half g_ffh[BT*Ee];
__device__ __half g_wt[(size_t)6 * Ll * Ee * Ee];    // 6 weight families, transposed [N][K] half
__device__ __half g_lmwt[(size_t)NPAD * Ee];         // LM head weight transposed [NPAD][Ee] half
__device__ float  g_rowloss[BT];
__device__ float  g_logits_scratch[205852672ull];    // fallback logits buffer

// ---------------- helpers ----------------
__device__ __forceinline__ uint32_t f2tf(float f){
  uint32_t u; asm("cvt.rna.tf32.f32 %0, %1;" : "=r"(u) : "f"(f)); return u;
}
__device__ __forceinline__ void mma8(float* c, const uint32_t* a, const uint32_t* b){
  asm volatile("mma.sync.aligned.m16n8k8.row.col.f32.tf32.tf32.f32 "
    "{%0,%1,%2,%3}, {%4,%5,%6,%7}, {%8,%9}, {%0,%1,%2,%3};"
    : "+f"(c[0]), "+f"(c[1]), "+f"(c[2]), "+f"(c[3])
    : "r"(a[0]), "r"(a[1]), "r"(a[2]), "r"(a[3]), "r"(b[0]), "r"(b[1]));
}
__device__ __forceinline__ void mma16(float* c, const uint32_t* a, const uint32_t* b){
  asm volatile("mma.sync.aligned.m16n8k16.row.col.f32.f16.f16.f32 "
    "{%0,%1,%2,%3}, {%4,%5,%6,%7}, {%8,%9}, {%0,%1,%2,%3};"
    : "+f"(c[0]), "+f"(c[1]), "+f"(c[2]), "+f"(c[3])
    : "r"(a[0]), "r"(a[1]), "r"(a[2]), "r"(a[3]), "r"(b[0]), "r"(b[1]));
}
__device__ __forceinline__ void cp16(void* smem_ptr, const void* g){
  uint32_t s = (uint32_t)__cvta_generic_to_shared(smem_ptr);
  asm volatile("cp.async.cg.shared.global [%0], [%1], 16;" :: "r"(s), "l"(g));
}
__device__ __forceinline__ void cp_commit(){ asm volatile("cp.async.commit_group;"); }
template<int N> __device__ __forceinline__ void cp_wait(){
  asm volatile("cp.async.wait_group %0;" :: "n"(N));
}

__device__ __forceinline__ float warpSum(float v){
  #pragma unroll
  for (int o = 16; o > 0; o >>= 1) v += __shfl_down_sync(0xffffffffu, v, o);
  return v;
}
__device__ __forceinline__ float warpMax(float v){
  #pragma unroll
  for (int o = 16; o > 0; o >>= 1) v = fmaxf(v, __shfl_down_sync(0xffffffffu, v, o));
  return v;
}
template<int OP>
__device__ __forceinline__ float blockReduce(float v){
  __shared__ float sh[33];
  int lane = threadIdx.x & 31, wid = threadIdx.x >> 5;
  v = OP ? warpMax(v) : warpSum(v);
  __syncthreads();
  if (lane == 0) sh[wid] = v;
  __syncthreads();
  int nw = blockDim.x >> 5;
  if (wid == 0){
    float u = (lane < nw) ? sh[lane] : (OP ? -INFINITY : 0.0f);
    u = OP ? warpMax(u) : warpSum(u);
    if (lane == 0) sh[32] = u;
  }
  __syncthreads();
  return sh[32];
}

// ---------------- embedding (fp32 residual) ----------------
__global__ void embed_kernel(const int* __restrict__ idx,
                             const float* __restrict__ tok,
                             const float* __restrict__ pos){
  int i  = blockIdx.x * 256 + threadIdx.x;
  int e4 = i & (Ee/4 - 1);
  int bt = i >> 8;
  int t  = bt & (Tt - 1);
  int token = idx[bt];
  float4 tv = ((const float4*)(tok + (size_t)token * Ee))[e4];
  float4 pv = ((const float4*)(pos + (size_t)t     * Ee))[e4];
  ((float4*)(g_x + (size_t)bt * Ee))[e4] =
      make_float4(tv.x*pv.x, tv.y*pv.y, tv.z*pv.z, tv.w*pv.w);
}

// ---------------- layernorm: fp32 in -> half out ----------------
__global__ void ln_kernel(const float* __restrict__ in, __half* __restrict__ out,
                          const float* __restrict__ w, const float* __restrict__ b){
  int row = blockIdx.x;
  float4 v = ((const float4*)(in + (size_t)row * Ee))[threadIdx.x];
  float mu = blockReduce<0>(v.x + v.y + v.z + v.w) * (1.0f / Ee);
  float dx = v.x - mu, dy = v.y - mu, dz = v.z - mu, dw = v.w - mu;
  float var = blockReduce<0>(dx*dx + dy*dy + dz*dz + dw*dw) * (1.0f / Ee);
  float rs = rsqrtf(var + 1e-5f);
  float4 wv = ((const float4*)w)[threadIdx.x];
  float4 bv = ((const float4*)b)[threadIdx.x];
  __half2* op = (__half2*)(out + (size_t)row * Ee) + threadIdx.x * 2;
  op[0] = __floats2half2_rn(dx*rs*wv.x + bv.x, dy*rs*wv.y + bv.y);
  op[1] = __floats2half2_rn(dz*rs*wv.z + bv.z, dw*rs*wv.w + bv.w);
}

// ---------------- weight transpose+half repack: src[K][N] f32 -> dst[N][K] half ----------------
__global__ void transpose_w(const float* __restrict__ src, __half* __restrict__ dst){
  __shared__ float t[32][33];
  size_t base = (size_t)blockIdx.z * Ee * Ee;
  int k0 = blockIdx.x * 32, n0 = blockIdx.y * 32;
  int tx = threadIdx.x, ty = threadIdx.y;  // 32 x 8
  #pragma unroll
  for (int i = 0; i < 4; i++)
    t[ty + i*8][tx] = src[base + (size_t)(k0 + ty + i*8) * Ee + n0 + tx];
  __syncthreads();
  #pragma unroll
  for (int i = 0; i < 4; i++)
    dst[base + (size_t)(n0 + ty + i*8) * Ee + k0 + tx] = __float2half(t[tx][ty + i*8]);
}

// LM head: src[Ee][Vv] f32 -> dst[NPAD][Ee] half (zero-padded rows)
__global__ void transpose_lm(const float* __restrict__ src, __half* __restrict__ dst){
  __shared__ float t[32][33];
  int k0 = blockIdx.x * 32, n0 = blockIdx.y * 32;
  int tx = threadIdx.x, ty = threadIdx.y;
  #pragma unroll
  for (int i = 0; i < 4; i++){
    int n = n0 + tx;
    t[ty + i*8][tx] = (n < Vv) ? src[(size_t)(k0 + ty + i*8) * Vv + n] : 0.0f;
  }
  __syncthreads();
  #pragma unroll
  for (int i = 0; i < 4; i++)
    dst[(size_t)(n0 + ty + i*8) * Ee + k0 + tx] = __float2half(t[tx][ty + i*8]);
}

// ---------------- fp16 tensor-core GEMM, 3-stage cp.async pipeline ----------------
// C[M,N] = act(A[M,K]@Bt[N,K]^T + bias)(+resid). BM=BN=128, BK=32, mma m16n8k16.
// A, Bt half, k-contiguous rows. bias/resid fp32. OUTH: half output else float.
#define HPITCH 40                        // halfs per smem row (20 words; conflict-free)
#define TILEH  (128*HPITCH)              // 5120 halfs per operand tile
#define STAGEH (2*TILEH)                 // 10240 halfs per stage
#define SGEMM_SMEM (3*STAGEH*2)          // 61440 bytes

template<bool RELU, bool RESID, bool OUTH>
__global__ __launch_bounds__(256, 2)
void sgemm_hc(const __half* __restrict__ A, const __half* __restrict__ Bt,
              const float* __restrict__ bias, const float* __restrict__ resid,
              void* __restrict__ C, int M, int N, int K, int Kb){
  extern __shared__ __align__(16) __half hsm[];
  int tid = threadIdx.x;
  int lane = tid & 31, warp = tid >> 5;
  int wm = warp >> 2, wn = warp & 3;
  int qk = lane & 3, qm = lane >> 2;
  int row0 = blockIdx.x * 128, col0 = blockIdx.y * 128;
  float acc[4][4][4] = {};

  auto prefetch = [&](int kt, int s){
    __half* As = hsm + s * STAGEH;
    __half* Bs = As + TILEH;
    #pragma unroll
    for (int l = 0; l < 2; l++){
      int f = tid + l * 256;                 // 512 chunks: 128 rows x 4 x 16B
      int r = f >> 2, c8 = (f & 3) << 3;
      cp16(As + r * HPITCH + c8, A  + (size_t)(row0 + r) * K  + kt + c8);
    }
    #pragma unroll
    for (int l = 0; l < 2; l++){
      int f = tid + l * 256;
      int r = f >> 2, c8 = (f & 3) << 3;
      cp16(Bs + r * HPITCH + c8, Bt + (size_t)(col0 + r) * Kb + kt + c8);
    }
  };

  int nk = K >> 5;
  prefetch(0, 0);  cp_commit();
  prefetch(32, 1); cp_commit();

  for (int t = 0; t < nk; t++){
    if (t < nk - 1) cp_wait<1>(); else cp_wait<0>();
    __syncthreads();
    const __half* As = hsm + (t % 3) * STAGEH;
    const __half* Bs = As + TILEH;
    #pragma unroll
    for (int ks = 0; ks < 2; ks++){
      int k0 = ks * 16;
      uint32_t af[4][4], bf[4][2];
      #pragma unroll
      for (int mi = 0; mi < 4; mi++){
        int mb = wm * 64 + mi * 16 + qm;
        af[mi][0] = *(const uint32_t*)&As[(mb    ) * HPITCH + k0 + qk*2    ];
        af[mi][1] = *(const uint32_t*)&As[(mb + 8) * HPITCH + k0 + qk*2    ];
        af[mi][2] = *(const uint32_t*)&As[(mb    ) * HPITCH + k0 + qk*2 + 8];
        af[mi][3] = *(const uint32_t*)&As[(mb + 8) * HPITCH + k0 + qk*2 + 8];
      }
      #pragma unroll
      for (int ni = 0; ni < 4; ni++){
        int nb = wn * 32 + ni * 8 + qm;
        bf[ni][0] = *(const uint32_t*)&Bs[nb * HPITCH + k0 + qk*2    ];
        bf[ni][1] = *(const uint32_t*)&Bs[nb * HPITCH + k0 + qk*2 + 8];
      }
      #pragma unroll
      for (int mi = 0; mi < 4; mi++)
        #pragma unroll
        for (int ni = 0; ni < 4; ni++)
          mma16(acc[mi][ni], af[mi], bf[ni]);
    }
    __syncthreads();
    if (t + 2 < nk){ prefetch((t + 2) << 5, (t + 2) % 3); cp_commit(); }
  }

  #pragma unroll
  for (int mi = 0; mi < 4; mi++){
    int r = row0 + wm * 64 + mi * 16 + qm;
    #pragma unroll
    for (int ni = 0; ni < 4; ni++){
      int c = col0 + wn * 32 + ni * 8 + qk * 2;
      #pragma unroll
      for (int half_ = 0; half_ < 2; half_++){
        int rr = r + half_ * 8;
        float v0 = acc[mi][ni][half_ * 2 + 0];
        float v1 = acc[mi][ni][half_ * 2 + 1];
        if (bias){ if (c < N) v0 += bias[c]; if (c + 1 < N) v1 += bias[c + 1]; }
        if (RELU){ v0 = fmaxf(v0, 0.0f); v1 = fmaxf(v1, 0.0f); }
        if (RESID){
          const float* rp = resid + (size_t)rr * N;
          if (c < N) v0 += rp[c];
          if (c + 1 < N) v1 += rp[c + 1];
        }
        if (OUTH){
          __half* cp = (__half*)C + (size_t)rr * N;
          if (c + 1 < N) *(__half2*)(cp + c) = __floats2half2_rn(v0, v1);
          else if (c < N) cp[c] = __float2half(v0);
        } else {
          float* cp = (float*)C + (size_t)rr * N;
          if (((N & 1) == 0) && c + 1 < N) *(float2*)(cp + c) = make_float2(v0, v1);
          else {
            if (c     < N) cp[c    ] = v0;
            if (c + 1 < N) cp[c + 1] = v1;
          }
        }
      }
    }
  }
}

// ---------------- fused flash attention (causal, tf32 mma, half IO) ----------------
#define KPITCH 68
#define VPITCH 72
#define PPITCH 68
#define FLASH_SMEM ((64*KPITCH + 64*VPITCH + 64*PPITCH) * 4)   // 53248 B

__global__ __launch_bounds__(128)
void flash_attn(const __half* __restrict__ q, const __half* __restrict__ k,
                const __half* __restrict__ v){
  extern __shared__ __align__(16) float fsm[];
  float*    Ks  = fsm;
  float*    Vs  = fsm + 64 * KPITCH;
  float*    Ps  = Vs  + 64 * VPITCH;
  uint32_t* KsU = (uint32_t*)Ks;
  uint32_t* VsU = (uint32_t*)Vs;
  uint32_t* PsU = (uint32_t*)Ps;

  int it = blockIdx.x, bh = blockIdx.y;
  int b = bh >> 4, hd = bh & 15;
  const __half* qh = q + (size_t)b * Tt * Ee + hd * Dd;
  const __half* kh = k + (size_t)b * Tt * Ee + hd * Dd;
  const __half* vh = v + (size_t)b * Tt * Ee + hd * Dd;

  int tid = threadIdx.x;
  int lane = tid & 31, warp = tid >> 5;
  int qk = lane & 3, qm = lane >> 2;
  int r0 = warp * 16;

  // stage Q tile (64x64) through Ps (as fp32), build per-warp A-frags
  #pragma unroll
  for (int l = 0; l < 4; l++){
    int f = tid + l * 128;                      // 512 chunks of 8 halfs
    int r = f >> 3, c8 = (f & 7) << 3;
    uint4 u = *(const uint4*)(qh + (size_t)(it * 64 + r) * Ee + c8);
    const __half2* hp = (const __half2*)&u;
    float* d = &Ps[r * PPITCH + c8];
    #pragma unroll
    for (int j = 0; j < 4; j++){
      float2 f2 = __half22float2(hp[j]);
      d[j*2] = f2.x; d[j*2+1] = f2.y;
    }
  }
  __syncthreads();
  uint32_t aq[8][4];
  #pragma unroll
  for (int ks = 0; ks < 8; ks++){
    aq[ks][0] = f2tf(Ps[(r0 + qm    ) * PPITCH + ks * 8 + qk]);
    aq[ks][1] = f2tf(Ps[(r0 + qm + 8) * PPITCH + ks * 8 + qk]);
    aq[ks][2] = f2tf(Ps[(r0 + qm    ) * PPITCH + ks * 8 + qk + 4]);
    aq[ks][3] = f2tf(Ps[(r0 + qm + 8) * PPITCH + ks * 8 + qk + 4]);
  }

  float oacc[8][4] = {};
  float mold[2] = {-INFINITY, -INFINITY};
  float lrun[2] = {0.0f, 0.0f};
  const float scale = 0.03125f;   // E^{-1/2}

  for (int jt = 0; jt <= it; jt++){
    __syncthreads();
    #pragma unroll
    for (int l = 0; l < 4; l++){
      int f = tid + l * 128;
      int r = f >> 3, c8 = (f & 7) << 3;
      uint4 uk = *(const uint4*)(kh + (size_t)(jt * 64 + r) * Ee + c8);
      const __half2* hk = (const __half2*)&uk;
      uint32_t* kd = &KsU[r * KPITCH + c8];
      #pragma unroll
      for (int j = 0; j < 4; j++){
        float2 f2 = __half22float2(hk[j]);
        kd[j*2] = f2tf(f2.x); kd[j*2+1] = f2tf(f2.y);
      }
      uint4 uv = *(const uint4*)(vh + (size_t)(jt * 64 + r) * Ee + c8);
      const __half2* hv = (const __half2*)&uv;
      uint32_t* vd = &VsU[r * VPITCH + c8];
      #pragma unroll
      for (int j = 0; j < 4; j++){
        float2 f2 = __half22float2(hv[j]);
        vd[j*2] = f2tf(f2.x); vd[j*2+1] = f2tf(f2.y);
      }
    }
    __syncthreads();

    float sacc[8][4] = {};
    #pragma unroll
    for (int ks = 0; ks < 8; ks++){
      #pragma unroll
      for (int ni = 0; ni < 8; ni++){
        uint32_t ub[2];
        ub[0] = KsU[(ni * 8 + qm) * KPITCH + ks * 8 + qk];
        ub[1] = KsU[(ni * 8 + qm) * KPITCH + ks * 8 + qk + 4];
        mma8(sacc[ni], aq[ks], ub);
      }
    }

    bool diag = (jt == it);
    #pragma unroll
    for (int ni = 0; ni < 8; ni++)
      #pragma unroll
      for (int e = 0; e < 4; e++){
        float sv = sacc[ni][e] * scale;
        if (diag){
          int rr = r0 + qm + ((e >> 1) << 3);
          int cc = ni * 8 + (qk << 1) + (e & 1);
          if (cc > rr) sv = -INFINITY;
        }
        sacc[ni][e] = sv;
      }

    #pragma unroll
    for (int h = 0; h < 2; h++){
      float mr = -INFINITY;
      #pragma unroll
      for (int ni = 0; ni < 8; ni++)
        mr = fmaxf(mr, fmaxf(sacc[ni][h * 2], sacc[ni][h * 2 + 1]));
      mr = fmaxf(mr, __shfl_xor_sync(0xffffffffu, mr, 1));
      mr = fmaxf(mr, __shfl_xor_sync(0xffffffffu, mr, 2));
      float mn = fmaxf(mold[h], mr);
      float alpha = __expf(mold[h] - mn);
      mold[h] = mn;
      float ls = 0.0f;
      int prow = (r0 + qm + h * 8) * PPITCH;
      #pragma unroll
      for (int ni = 0; ni < 8; ni++){
        float p0 = __expf(sacc[ni][h * 2    ] - mn);
        float p1 = __expf(sacc[ni][h * 2 + 1] - mn);
        ls += p0 + p1;
        PsU[prow + ni * 8 + qk * 2    ] = f2tf(p0);
        PsU[prow + ni * 8 + qk * 2 + 1] = f2tf(p1);
        oacc[ni][h * 2    ] *= alpha;
        oacc[ni][h * 2 + 1] *= alpha;
      }
      ls += __shfl_xor_sync(0xffffffffu, ls, 1);
      ls += __shfl_xor_sync(0xffffffffu, ls, 2);
      lrun[h] = lrun[h] * alpha + ls;
    }
    __syncwarp();

    #pragma unroll
    for (int ks = 0; ks < 8; ks++){
      uint32_t ua[4];
      ua[0] = PsU[(r0 + qm    ) * PPITCH + ks * 8 + qk];
      ua[1] = PsU[(r0 + qm + 8) * PPITCH + ks * 8 + qk];
      ua[2] = PsU[(r0 + qm    ) * PPITCH + ks * 8 + qk + 4];
      ua[3] = PsU[(r0 + qm + 8) * PPITCH + ks * 8 + qk + 4];
      #pragma unroll
      for (int ni = 0; ni < 8; ni++){
        uint32_t ub[2];
        ub[0] = VsU[(ks * 8 + qk    ) * VPITCH + ni * 8 + qm];
        ub[1] = VsU[(ks * 8 + qk + 4) * VPITCH + ni * 8 + qm];
        mma8(oacc[ni], ua, ub);
      }
    }
  }

  #pragma unroll
  for (int h = 0; h < 2; h++){
    float inv = 1.0f / lrun[h];
    int gi = it * 64 + r0 + qm + h * 8;
    __half* op = g_oh + (size_t)(b * Tt + gi) * Ee + hd * Dd;
    #pragma unroll
    for (int ni = 0; ni < 8; ni++)
      *(__half2*)(op + ni * 8 + qk * 2) =
          __floats2half2_rn(oacc[ni][h * 2] * inv, oacc[ni][h * 2 + 1] * inv);
  }
}

// ---------------- loss ----------------
__global__ void loss_row(const float* __restrict__ logits, const int* __restrict__ tgt){
  int r = blockIdx.x;
  const float* lp = logits + (size_t)r * Vv;
  float m = -INFINITY;
  for (int c = threadIdx.x; c < Vv; c += 256) m = fmaxf(m, lp[c]);
  m = blockReduce<1>(m);
  float s = 0.0f;
  for (int c = threadIdx.x; c < Vv; c += 256) s += __expf(lp[c] - m);
  s = blockReduce<0>(s);
  if (threadIdx.x == 0) g_rowloss[r] = -(lp[tgt[r]] - m - logf(s));
}
__global__ void loss_final(float* __restrict__ out){
  float s = 0.0f;
  for (int i = threadIdx.x; i < BT; i += 256) s += g_rowloss[i];
  s = blockReduce<0>(s);
  if (threadIdx.x == 0) out[0] = s / (float)BT;
}

// ---------------- launch ----------------
extern "C" void kernel_launch(void* const* d_in, const int* in_sizes, int n_in,
                              void* d_out, int out_size){
  const int*   idx     = (const int*)  d_in[0];
  const int*   targets = (const int*)  d_in[1];
  const float* tok     = (const float*)d_in[2];
  const float* pos     = (const float*)d_in[3];
  const float* ln1w    = (const float*)d_in[4];
  const float* ln1b    = (const float*)d_in[5];
  const float* Wq      = (const float*)d_in[6];
  const float* Wk      = (const float*)d_in[7];
  const float* Wv      = (const float*)d_in[8];
  const float* projw   = (const float*)d_in[9];
  const float* projb   = (const float*)d_in[10];
  const float* ln2w    = (const float*)d_in[11];
  const float* ln2b    = (const float*)d_in[12];
  const float* fw1     = (const float*)d_in[13];
  const float* fb1     = (const float*)d_in[14];
  const float* fw2     = (const float*)d_in[15];
  const float* fb2     = (const float*)d_in[16];
  const float* lnfw    = (const float*)d_in[17];
  const float* lnfb    = (const float*)d_in[18];
  const float* lmw     = (const float*)d_in[19];
  const float* lmb     = (const float*)d_in[20];

  float  *x, *scratch;
  __half *hh, *qh, *kh, *vh, *oh, *ffh, *wt, *lmwt;
  cudaGetSymbolAddress((void**)&x,   g_x);
  cudaGetSymbolAddress((void**)&hh,  g_hh);
  cudaGetSymbolAddress((void**)&qh,  g_qh);
  cudaGetSymbolAddress((void**)&kh,  g_kh);
  cudaGetSymbolAddress((void**)&vh,  g_vh);
  cudaGetSymbolAddress((void**)&oh,  g_oh);
  cudaGetSymbolAddress((void**)&ffh, g_ffh);
  cudaGetSymbolAddress((void**)&wt,  g_wt);
  cudaGetSymbolAddress((void**)&lmwt, g_lmwt);
  cudaGetSymbolAddress((void**)&scratch, g_logits_scratch);

  cudaFuncSetAttribute(sgemm_hc<false,false,true >, cudaFuncAttributeMaxDynamicSharedMemorySize, SGEMM_SMEM);
  cudaFuncSetAttribute(sgemm_hc<false,true ,false>, cudaFuncAttributeMaxDynamicSharedMemorySize, SGEMM_SMEM);
  cudaFuncSetAttribute(sgemm_hc<true ,false,true >, cudaFuncAttributeMaxDynamicSharedMemorySize, SGEMM_SMEM);
  cudaFuncSetAttribute(sgemm_hc<false,false,false>, cudaFuncAttributeMaxDynamicSharedMemorySize, SGEMM_SMEM);
  cudaFuncSetAttribute(flash_attn, cudaFuncAttributeMaxDynamicSharedMemorySize, FLASH_SMEM);

  const long long bt_v = (long long)BT * Vv;
  float* logits = ((long long)out_size >= bt_v) ? (float*)d_out : scratch;

  embed_kernel<<<BT * Ee / 4 / 256, 256>>>(idx, tok, pos);

  // one-shot weight repacks (transpose + fp16)
  const size_t FAM = (size_t)Ll * Ee * Ee;
  dim3 tb(32, 8), tg(Ee/32, Ee/32, Ll);
  transpose_w<<<tg, tb>>>(Wq,    wt + 0*FAM);
  transpose_w<<<tg, tb>>>(Wk,    wt + 1*FAM);
  transpose_w<<<tg, tb>>>(Wv,    wt + 2*FAM);
  transpose_w<<<tg, tb>>>(projw, wt + 3*FAM);
  transpose_w<<<tg, tb>>>(fw1,   wt + 4*FAM);
  transpose_w<<<tg, tb>>>(fw2,   wt + 5*FAM);
  transpose_lm<<<dim3(Ee/32, NPAD/32), tb>>>(lmw, lmwt);

  dim3 gEE(BT / 128, Ee / 128);      // x = M blocks, y = N blocks
  dim3 gAttn(Tt / 64, Bb * Hh);
  const size_t WL = (size_t)Ee * Ee;
  for (int l = 0; l < Ll; l++){
    size_t wo = (size_t)l * WL, bo = (size_t)l * Ee;
    ln_kernel<<<BT, 256>>>(x, hh, ln1w + bo, ln1b + bo);
    sgemm_hc<false,false,true ><<<gEE, 256, SGEMM_SMEM>>>(hh, wt + 0*FAM + wo, nullptr, nullptr, qh, BT, Ee, Ee, Ee);
    sgemm_hc<false,false,true ><<<gEE, 256, SGEMM_SMEM>>>(hh, wt + 1*FAM + wo, nullptr, nullptr, kh, BT, Ee, Ee, Ee);
    sgemm_hc<false,false,true ><<<gEE, 256, SGEMM_SMEM>>>(hh, wt + 2*FAM + wo, nullptr, nullptr, vh, BT, Ee, Ee, Ee);
    flash_attn<<<gAttn, 128, FLASH_SMEM>>>(qh, kh, vh);
    sgemm_hc<false,true ,false><<<gEE, 256, SGEMM_SMEM>>>(oh,  wt + 3*FAM + wo, projb + bo, x, x, BT, Ee, Ee, Ee);
    ln_kernel<<<BT, 256>>>(x, hh, ln2w + bo, ln2b + bo);
    sgemm_hc<true ,false,true ><<<gEE, 256, SGEMM_SMEM>>>(hh,  wt + 4*FAM + wo, fb1 + bo, nullptr, ffh, BT, Ee, Ee, Ee);
    sgemm_hc<false,true ,false><<<gEE, 256, SGEMM_SMEM>>>(ffh, wt + 5*FAM + wo, fb2 + bo, x, x, BT, Ee, Ee, Ee);
  }

  ln_kernel<<<BT, 256>>>(x, hh, lnfw, lnfb);
  sgemm_hc<false,false,false><<<dim3(BT / 128, NPAD / 128), 256, SGEMM_SMEM>>>(
      hh, lmwt, lmb, nullptr, logits, BT, Vv, Ee, Ee);

  if ((long long)out_size != bt_v){
    loss_row<<<BT, 256>>>(logits, targets);
    float* lossptr = ((long long)out_size > bt_v) ? ((float*)d_out) + bt_v
                                                  : (float*)d_out;
    loss_final<<<1, 256>>>(lossptr);
  }
}

// round 8
// speedup vs baseline: 5.8186x; 1.1060x over previous
#include <cuda_runtime.h>
#include <cuda_fp16.h>
#include <math.h>
#include <stdint.h>

#define Bb 4
#define Tt 1024
#define Vv 50257
#define Ee 1024
#define Hh 16
#define Ll 8
#define Dd 64
#define BT (Bb*Tt)
#define NPAD 50304   // Vv padded to multiple of 128

// ---------------- device scratch (static, allocation-free) ----------------
__device__ float  g_x [BT*Ee];                       // fp32 residual stream
__device__ __half g_hh[BT*Ee];                       // LN output (GEMM A)
__device__ __half g_qh[BT*Ee];
__device__ __half g_kh[BT*Ee];
__device__ __half g_vh[BT*Ee];
__device__ __half g_oh[BT*Ee];
__device__ __half g_ffh[BT*Ee];
__device__ __half g_wt[(size_t)6 * Ll * Ee * Ee];    // weights transposed [N][K] half
__device__ __half g_lmwt[(size_t)NPAD * Ee];         // LM head transposed [NPAD][Ee] half
__device__ float  g_rowloss[BT];
__device__ float  g_logits_scratch[205852672ull];    // fallback logits buffer

// ---------------- helpers ----------------
__device__ __forceinline__ uint32_t f2tf(float f){
  uint32_t u; asm("cvt.rna.tf32.f32 %0, %1;" : "=r"(u) : "f"(f)); return u;
}
__device__ __forceinline__ void mma8(float* c, const uint32_t* a, const uint32_t* b){
  asm volatile("mma.sync.aligned.m16n8k8.row.col.f32.tf32.tf32.f32 "
    "{%0,%1,%2,%3}, {%4,%5,%6,%7}, {%8,%9}, {%0,%1,%2,%3};"
    : "+f"(c[0]), "+f"(c[1]), "+f"(c[2]), "+f"(c[3])
    : "r"(a[0]), "r"(a[1]), "r"(a[2]), "r"(a[3]), "r"(b[0]), "r"(b[1]));
}
__device__ __forceinline__ void mma16(float* c, const uint32_t* a, const uint32_t* b){
  asm volatile("mma.sync.aligned.m16n8k16.row.col.f32.f16.f16.f32 "
    "{%0,%1,%2,%3}, {%4,%5,%6,%7}, {%8,%9}, {%0,%1,%2,%3};"
    : "+f"(c[0]), "+f"(c[1]), "+f"(c[2]), "+f"(c[3])
    : "r"(a[0]), "r"(a[1]), "r"(a[2]), "r"(a[3]), "r"(b[0]), "r"(b[1]));
}
__device__ __forceinline__ void ldsm_x4(uint32_t& r0, uint32_t& r1,
                                        uint32_t& r2, uint32_t& r3, uint32_t addr){
  asm volatile("ldmatrix.sync.aligned.m8n8.x4.shared.b16 {%0,%1,%2,%3}, [%4];"
    : "=r"(r0), "=r"(r1), "=r"(r2), "=r"(r3) : "r"(addr));
}
__device__ __forceinline__ void cp16(void* smem_ptr, const void* g){
  uint32_t s = (uint32_t)__cvta_generic_to_shared(smem_ptr);
  asm volatile("cp.async.cg.shared.global [%0], [%1], 16;" :: "r"(s), "l"(g));
}
__device__ __forceinline__ void cp_commit(){ asm volatile("cp.async.commit_group;"); }
template<int N> __device__ __forceinline__ void cp_wait(){
  asm volatile("cp.async.wait_group %0;" :: "n"(N));
}
__device__ __forceinline__ uint32_t smem_u32(const void* p){
  return (uint32_t)__cvta_generic_to_shared(p);
}

__device__ __forceinline__ float warpSum(float v){
  #pragma unroll
  for (int o = 16; o > 0; o >>= 1) v += __shfl_down_sync(0xffffffffu, v, o);
  return v;
}
__device__ __forceinline__ float warpMax(float v){
  #pragma unroll
  for (int o = 16; o > 0; o >>= 1) v = fmaxf(v, __shfl_down_sync(0xffffffffu, v, o));
  return v;
}
template<int OP>
__device__ __forceinline__ float blockReduce(float v){
  __shared__ float sh[33];
  int lane = threadIdx.x & 31, wid = threadIdx.x >> 5;
  v = OP ? warpMax(v) : warpSum(v);
  __syncthreads();
  if (lane == 0) sh[wid] = v;
  __syncthreads();
  int nw = blockDim.x >> 5;
  if (wid == 0){
    float u = (lane < nw) ? sh[lane] : (OP ? -INFINITY : 0.0f);
    u = OP ? warpMax(u) : warpSum(u);
    if (lane == 0) sh[32] = u;
  }
  __syncthreads();
  return sh[32];
}

// ---------------- embedding (fp32 residual) ----------------
__global__ void embed_kernel(const int* __restrict__ idx,
                             const float* __restrict__ tok,
                             const float* __restrict__ pos){
  int i  = blockIdx.x * 256 + threadIdx.x;
  int e4 = i & (Ee/4 - 1);
  int bt = i >> 8;
  int t  = bt & (Tt - 1);
  int token = idx[bt];
  float4 tv = ((const float4*)(tok + (size_t)token * Ee))[e4];
  float4 pv = ((const float4*)(pos + (size_t)t     * Ee))[e4];
  ((float4*)(g_x + (size_t)bt * Ee))[e4] =
      make_float4(tv.x*pv.x, tv.y*pv.y, tv.z*pv.z, tv.w*pv.w);
}

// ---------------- layernorm: fp32 in -> half out ----------------
__global__ void ln_kernel(const float* __restrict__ in, __half* __restrict__ out,
                          const float* __restrict__ w, const float* __restrict__ b){
  int row = blockIdx.x;
  float4 v = ((const float4*)(in + (size_t)row * Ee))[threadIdx.x];
  float mu = blockReduce<0>(v.x + v.y + v.z + v.w) * (1.0f / Ee);
  float dx = v.x - mu, dy = v.y - mu, dz = v.z - mu, dw = v.w - mu;
  float var = blockReduce<0>(dx*dx + dy*dy + dz*dz + dw*dw) * (1.0f / Ee);
  float rs = rsqrtf(var + 1e-5f);
  float4 wv = ((const float4*)w)[threadIdx.x];
  float4 bv = ((const float4*)b)[threadIdx.x];
  __half2* op = (__half2*)(out + (size_t)row * Ee) + threadIdx.x * 2;
  op[0] = __floats2half2_rn(dx*rs*wv.x + bv.x, dy*rs*wv.y + bv.y);
  op[1] = __floats2half2_rn(dz*rs*wv.z + bv.z, dw*rs*wv.w + bv.w);
}

// ---------------- weight transpose+half repack: src[K][N] f32 -> dst[N][K] half ----------------
__global__ void transpose_w(const float* __restrict__ src, __half* __restrict__ dst){
  __shared__ float t[32][33];
  size_t base = (size_t)blockIdx.z * Ee * Ee;
  int k0 = blockIdx.x * 32, n0 = blockIdx.y * 32;
  int tx = threadIdx.x, ty = threadIdx.y;  // 32 x 8
  #pragma unroll
  for (int i = 0; i < 4; i++)
    t[ty + i*8][tx] = src[base + (size_t)(k0 + ty + i*8) * Ee + n0 + tx];
  __syncthreads();
  #pragma unroll
  for (int i = 0; i < 4; i++)
    dst[base + (size_t)(n0 + ty + i*8) * Ee + k0 + tx] = __float2half(t[tx][ty + i*8]);
}

// LM head: src[Ee][Vv] f32 -> dst[NPAD][Ee] half (zero-padded rows)
__global__ void transpose_lm(const float* __restrict__ src, __half* __restrict__ dst){
  __shared__ float t[32][33];
  int k0 = blockIdx.x * 32, n0 = blockIdx.y * 32;
  int tx = threadIdx.x, ty = threadIdx.y;
  #pragma unroll
  for (int i = 0; i < 4; i++){
    int n = n0 + tx;
    t[ty + i*8][tx] = (n < Vv) ? src[(size_t)(k0 + ty + i*8) * Vv + n] : 0.0f;
  }
  __syncthreads();
  #pragma unroll
  for (int i = 0; i < 4; i++)
    dst[(size_t)(n0 + ty + i*8) * Ee + k0 + tx] = __float2half(t[tx][ty + i*8]);
}

// ---------------- fp16 tensor-core GEMM, 3-stage cp.async + ldmatrix ----------------
// C[M,N] = act(A[M,K]@Bt[N,K]^T + bias)(+resid). BM=BN=128, BK=32, mma m16n8k16.
#define HPITCH 40                        // halfs per smem row (conflict-free for LDSM)
#define TILEH  (128*HPITCH)              // 5120 halfs per operand tile
#define STAGEH (2*TILEH)                 // 10240 halfs per stage
#define SGEMM_SMEM (3*STAGEH*2)          // 61440 bytes

template<bool RELU, bool RESID, bool OUTH>
__global__ __launch_bounds__(256, 2)
void sgemm_hc(const __half* __restrict__ A, const __half* __restrict__ Bt,
              const float* __restrict__ bias, const float* __restrict__ resid,
              void* __restrict__ C, int M, int N, int K, int Kb){
  extern __shared__ __align__(16) __half hsm[];
  int tid = threadIdx.x;
  int lane = tid & 31, warp = tid >> 5;
  int wm = warp >> 2, wn = warp & 3;
  int qk = lane & 3, qm = lane >> 2;
  int row0 = blockIdx.x * 128, col0 = blockIdx.y * 128;
  float acc[4][4][4] = {};

  // per-lane ldmatrix offsets (in half units)
  int j8 = lane >> 3, r8 = lane & 7;
  int a_off[4], b_off[2];
  #pragma unroll
  for (int mi = 0; mi < 4; mi++)
    a_off[mi] = (wm*64 + mi*16 + ((j8 & 1) << 3) + r8) * HPITCH + ((j8 >> 1) << 3);
  #pragma unroll
  for (int p = 0; p < 2; p++)
    b_off[p] = (wn*32 + (p*2 + (j8 >> 1))*8 + r8) * HPITCH + ((j8 & 1) << 3);

  auto prefetch = [&](int kt, int s){
    __half* As = hsm + s * STAGEH;
    __half* Bs = As + TILEH;
    #pragma unroll
    for (int l = 0; l < 2; l++){
      int f = tid + l * 256;                 // 512 chunks: 128 rows x 4 x 16B
      int r = f >> 2, c8 = (f & 3) << 3;
      cp16(As + r * HPITCH + c8, A  + (size_t)(row0 + r) * K  + kt + c8);
    }
    #pragma unroll
    for (int l = 0; l < 2; l++){
      int f = tid + l * 256;
      int r = f >> 2, c8 = (f & 3) << 3;
      cp16(Bs + r * HPITCH + c8, Bt + (size_t)(col0 + r) * Kb + kt + c8);
    }
  };

  int nk = K >> 5;
  prefetch(0, 0);  cp_commit();
  prefetch(32, 1); cp_commit();

  for (int t = 0; t < nk; t++){
    if (t < nk - 1) cp_wait<1>(); else cp_wait<0>();
    __syncthreads();
    uint32_t aU = smem_u32(hsm + (t % 3) * STAGEH);
    uint32_t bU = aU + TILEH * 2;
    #pragma unroll
    for (int ks = 0; ks < 2; ks++){
      int k0 = ks * 16;
      uint32_t af[4][4], bf[4][2];
      #pragma unroll
      for (int mi = 0; mi < 4; mi++)
        ldsm_x4(af[mi][0], af[mi][1], af[mi][2], af[mi][3],
                aU + (uint32_t)(a_off[mi] + k0) * 2);
      #pragma unroll
      for (int p = 0; p < 2; p++)
        ldsm_x4(bf[p*2][0], bf[p*2][1], bf[p*2+1][0], bf[p*2+1][1],
                bU + (uint32_t)(b_off[p] + k0) * 2);
      #pragma unroll
      for (int mi = 0; mi < 4; mi++)
        #pragma unroll
        for (int ni = 0; ni < 4; ni++)
          mma16(acc[mi][ni], af[mi], bf[ni]);
    }
    __syncthreads();
    if (t + 2 < nk){ prefetch((t + 2) << 5, (t + 2) % 3); cp_commit(); }
  }

  #pragma unroll
  for (int mi = 0; mi < 4; mi++){
    int r = row0 + wm * 64 + mi * 16 + qm;
    #pragma unroll
    for (int ni = 0; ni < 4; ni++){
      int c = col0 + wn * 32 + ni * 8 + qk * 2;
      #pragma unroll
      for (int half_ = 0; half_ < 2; half_++){
        int rr = r + half_ * 8;
        float v0 = acc[mi][ni][half_ * 2 + 0];
        float v1 = acc[mi][ni][half_ * 2 + 1];
        if (bias){ if (c < N) v0 += bias[c]; if (c + 1 < N) v1 += bias[c + 1]; }
        if (RELU){ v0 = fmaxf(v0, 0.0f); v1 = fmaxf(v1, 0.0f); }
        if (RESID){
          const float* rp = resid + (size_t)rr * N;
          if (c < N) v0 += rp[c];
          if (c + 1 < N) v1 += rp[c + 1];
        }
        if (OUTH){
          __half* cp = (__half*)C + (size_t)rr * N;
          if (c + 1 < N) *(__half2*)(cp + c) = __floats2half2_rn(v0, v1);
          else if (c < N) cp[c] = __float2half(v0);
        } else {
          float* cp = (float*)C + (size_t)rr * N;
          if (((N & 1) == 0) && c + 1 < N) *(float2*)(cp + c) = make_float2(v0, v1);
          else {
            if (c     < N) cp[c    ] = v0;
            if (c + 1 < N) cp[c + 1] = v1;
          }
        }
      }
    }
  }
}

// ---------------- fused flash attention (causal, tf32 mma, half IO) ----------------
#define KPITCH 68
#define VPITCH 72
#define PPITCH 68
#define FLASH_SMEM ((64*KPITCH + 64*VPITCH + 64*PPITCH) * 4)   // 53248 B

__global__ __launch_bounds__(128)
void flash_attn(const __half* __restrict__ q, const __half* __restrict__ k,
                const __half* __restrict__ v){
  extern __shared__ __align__(16) float fsm[];
  float*    Ks  = fsm;
  float*    Vs  = fsm + 64 * KPITCH;
  float*    Ps  = Vs  + 64 * VPITCH;
  uint32_t* KsU = (uint32_t*)Ks;
  uint32_t* VsU = (uint32_t*)Vs;
  uint32_t* PsU = (uint32_t*)Ps;

  int it = blockIdx.x, bh = blockIdx.y;
  int b = bh >> 4, hd = bh & 15;
  const __half* qh = q + (size_t)b * Tt * Ee + hd * Dd;
  const __half* kh = k + (size_t)b * Tt * Ee + hd * Dd;
  const __half* vh = v + (size_t)b * Tt * Ee + hd * Dd;

  int tid = threadIdx.x;
  int lane = tid & 31, warp = tid >> 5;
  int qk = lane & 3, qm = lane >> 2;
  int r0 = warp * 16;

  #pragma unroll
  for (int l = 0; l < 4; l++){
    int f = tid + l * 128;
    int r = f >> 3, c8 = (f & 7) << 3;
    uint4 u = *(const uint4*)(qh + (size_t)(it * 64 + r) * Ee + c8);
    const __half2* hp = (const __half2*)&u;
    float* d = &Ps[r * PPITCH + c8];
    #pragma unroll
    for (int j = 0; j < 4; j++){
      float2 f2 = __half22float2(hp[j]);
      d[j*2] = f2.x; d[j*2+1] = f2.y;
    }
  }
  __syncthreads();
  uint32_t aq[8][4];
  #pragma unroll
  for (int ks = 0; ks < 8; ks++){
    aq[ks][0] = f2tf(Ps[(r0 + qm    ) * PPITCH + ks * 8 + qk]);
    aq[ks][1] = f2tf(Ps[(r0 + qm + 8) * PPITCH + ks * 8 + qk]);
    aq[ks][2] = f2tf(Ps[(r0 + qm    ) * PPITCH + ks * 8 + qk + 4]);
    aq[ks][3] = f2tf(Ps[(r0 + qm + 8) * PPITCH + ks * 8 + qk + 4]);
  }

  float oacc[8][4] = {};
  float mold[2] = {-INFINITY, -INFINITY};
  float lrun[2] = {0.0f, 0.0f};
  const float scale = 0.03125f;

  for (int jt = 0; jt <= it; jt++){
    __syncthreads();
    #pragma unroll
    for (int l = 0; l < 4; l++){
      int f = tid + l * 128;
      int r = f >> 3, c8 = (f & 7) << 3;
      uint4 uk = *(const uint4*)(kh + (size_t)(jt * 64 + r) * Ee + c8);
      const __half2* hk = (const __half2*)&uk;
      uint32_t* kd = &KsU[r * KPITCH + c8];
      #pragma unroll
      for (int j = 0; j < 4; j++){
        float2 f2 = __half22float2(hk[j]);
        kd[j*2] = f2tf(f2.x); kd[j*2+1] = f2tf(f2.y);
      }
      uint4 uv = *(const uint4*)(vh + (size_t)(jt * 64 + r) * Ee + c8);
      const __half2* hv = (const __half2*)&uv;
      uint32_t* vd = &VsU[r * VPITCH + c8];
      #pragma unroll
      for (int j = 0; j < 4; j++){
        float2 f2 = __half22float2(hv[j]);
        vd[j*2] = f2tf(f2.x); vd[j*2+1] = f2tf(f2.y);
      }
    }
    __syncthreads();

    float sacc[8][4] = {};
    #pragma unroll
    for (int ks = 0; ks < 8; ks++){
      #pragma unroll
      for (int ni = 0; ni < 8; ni++){
        uint32_t ub[2];
        ub[0] = KsU[(ni * 8 + qm) * KPITCH + ks * 8 + qk];
        ub[1] = KsU[(ni * 8 + qm) * KPITCH + ks * 8 + qk + 4];
        mma8(sacc[ni], aq[ks], ub);
      }
    }

    bool diag = (jt == it);
    #pragma unroll
    for (int ni = 0; ni < 8; ni++)
      #pragma unroll
      for (int e = 0; e < 4; e++){
        float sv = sacc[ni][e] * scale;
        if (diag){
          int rr = r0 + qm + ((e >> 1) << 3);
          int cc = ni * 8 + (qk << 1) + (e & 1);
          if (cc > rr) sv = -INFINITY;
        }
        sacc[ni][e] = sv;
      }

    #pragma unroll
    for (int h = 0; h < 2; h++){
      float mr = -INFINITY;
      #pragma unroll
      for (int ni = 0; ni < 8; ni++)
        mr = fmaxf(mr, fmaxf(sacc[ni][h * 2], sacc[ni][h * 2 + 1]));
      mr = fmaxf(mr, __shfl_xor_sync(0xffffffffu, mr, 1));
      mr = fmaxf(mr, __shfl_xor_sync(0xffffffffu, mr, 2));
      float mn = fmaxf(mold[h], mr);
      float alpha = __expf(mold[h] - mn);
      mold[h] = mn;
      float ls = 0.0f;
      int prow = (r0 + qm + h * 8) * PPITCH;
      #pragma unroll
      for (int ni = 0; ni < 8; ni++){
        float p0 = __expf(sacc[ni][h * 2    ] - mn);
        float p1 = __expf(sacc[ni][h * 2 + 1] - mn);
        ls += p0 + p1;
        PsU[prow + ni * 8 + qk * 2    ] = f2tf(p0);
        PsU[prow + ni * 8 + qk * 2 + 1] = f2tf(p1);
        oacc[ni][h * 2    ] *= alpha;
        oacc[ni][h * 2 + 1] *= alpha;
      }
      ls += __shfl_xor_sync(0xffffffffu, ls, 1);
      ls += __shfl_xor_sync(0xffffffffu, ls, 2);
      lrun[h] = lrun[h] * alpha + ls;
    }
    __syncwarp();

    #pragma unroll
    for (int ks = 0; ks < 8; ks++){
      uint32_t ua[4];
      ua[0] = PsU[(r0 + qm    ) * PPITCH + ks * 8 + qk];
      ua[1] = PsU[(r0 + qm + 8) * PPITCH + ks * 8 + qk];
      ua[2] = PsU[(r0 + qm    ) * PPITCH + ks * 8 + qk + 4];
      ua[3] = PsU[(r0 + qm + 8) * PPITCH + ks * 8 + qk + 4];
      #pragma unroll
      for (int ni = 0; ni < 8; ni++){
        uint32_t ub[2];
        ub[0] = VsU[(ks * 8 + qk    ) * VPITCH + ni * 8 + qm];
        ub[1] = VsU[(ks * 8 + qk + 4) * VPITCH + ni * 8 + qm];
        mma8(oacc[ni], ua, ub);
      }
    }
  }

  #pragma unroll
  for (int h = 0; h < 2; h++){
    float inv = 1.0f / lrun[h];
    int gi = it * 64 + r0 + qm + h * 8;
    __half* op = g_oh + (size_t)(b * Tt + gi) * Ee + hd * Dd;
    #pragma unroll
    for (int ni = 0; ni < 8; ni++)
      *(__half2*)(op + ni * 8 + qk * 2) =
          __floats2half2_rn(oacc[ni][h * 2] * inv, oacc[ni][h * 2 + 1] * inv);
  }
}

// ---------------- loss: single-pass online logsumexp ----------------
__global__ void loss_row(const float* __restrict__ logits, const int* __restrict__ tgt){
  int r = blockIdx.x;
  const float* lp = logits + (size_t)r * Vv;
  int tid = threadIdx.x, lane = tid & 31, wid = tid >> 5;
  float m = -INFINITY, s = 0.0f;
  for (int c = tid; c < Vv; c += 256){
    float v = lp[c];
    if (v > m){ s = s * __expf(m - v) + 1.0f; m = v; }
    else s += __expf(v - m);
  }
  // warp pair-reduce
  #pragma unroll
  for (int o = 16; o > 0; o >>= 1){
    float mo = __shfl_down_sync(0xffffffffu, m, o);
    float so = __shfl_down_sync(0xffffffffu, s, o);
    float mn = fmaxf(m, mo);
    s = s * __expf(m - mn) + so * __expf(mo - mn);
    m = mn;
  }
  __shared__ float shm[8], shs[8];
  if (lane == 0){ shm[wid] = m; shs[wid] = s; }
  __syncthreads();
  if (tid == 0){
    float M = shm[0], S = shs[0];
    #pragma unroll
    for (int i = 1; i < 8; i++){
      float mn = fmaxf(M, shm[i]);
      S = S * __expf(M - mn) + shs[i] * __expf(shm[i] - mn);
      M = mn;
    }
    g_rowloss[r] = -(lp[tgt[r]] - M - logf(S));
  }
}
__global__ void loss_final(float* __restrict__ out){
  float s = 0.0f;
  for (int i = threadIdx.x; i < BT; i += 256) s += g_rowloss[i];
  s = blockReduce<0>(s);
  if (threadIdx.x == 0) out[0] = s / (float)BT;
}

// ---------------- launch ----------------
extern "C" void kernel_launch(void* const* d_in, const int* in_sizes, int n_in,
                              void* d_out, int out_size){
  const int*   idx     = (const int*)  d_in[0];
  const int*   targets = (const int*)  d_in[1];
  const float* tok     = (const float*)d_in[2];
  const float* pos     = (const float*)d_in[3];
  const float* ln1w    = (const float*)d_in[4];
  const float* ln1b    = (const float*)d_in[5];
  const float* Wq      = (const float*)d_in[6];
  const float* Wk      = (const float*)d_in[7];
  const float* Wv      = (const float*)d_in[8];
  const float* projw   = (const float*)d_in[9];
  const float* projb   = (const float*)d_in[10];
  const float* ln2w    = (const float*)d_in[11];
  const float* ln2b    = (const float*)d_in[12];
  const float* fw1     = (const float*)d_in[13];
  const float* fb1     = (const float*)d_in[14];
  const float* fw2     = (const float*)d_in[15];
  const float* fb2     = (const float*)d_in[16];
  const float* lnfw    = (const float*)d_in[17];
  const float* lnfb    = (const float*)d_in[18];
  const float* lmw     = (const float*)d_in[19];
  const float* lmb     = (const float*)d_in[20];

  float  *x, *scratch;
  __half *hh, *qh, *kh, *vh, *oh, *ffh, *wt, *lmwt;
  cudaGetSymbolAddress((void**)&x,   g_x);
  cudaGetSymbolAddress((void**)&hh,  g_hh);
  cudaGetSymbolAddress((void**)&qh,  g_qh);
  cudaGetSymbolAddress((void**)&kh,  g_kh);
  cudaGetSymbolAddress((void**)&vh,  g_vh);
  cudaGetSymbolAddress((void**)&oh,  g_oh);
  cudaGetSymbolAddress((void**)&ffh, g_ffh);
  cudaGetSymbolAddress((void**)&wt,  g_wt);
  cudaGetSymbolAddress((void**)&lmwt, g_lmwt);
  cudaGetSymbolAddress((void**)&scratch, g_logits_scratch);

  cudaFuncSetAttribute(sgemm_hc<false,false,true >, cudaFuncAttributeMaxDynamicSharedMemorySize, SGEMM_SMEM);
  cudaFuncSetAttribute(sgemm_hc<false,true ,false>, cudaFuncAttributeMaxDynamicSharedMemorySize, SGEMM_SMEM);
  cudaFuncSetAttribute(sgemm_hc<true ,false,true >, cudaFuncAttributeMaxDynamicSharedMemorySize, SGEMM_SMEM);
  cudaFuncSetAttribute(sgemm_hc<false,false,false>, cudaFuncAttributeMaxDynamicSharedMemorySize, SGEMM_SMEM);
  cudaFuncSetAttribute(flash_attn, cudaFuncAttributeMaxDynamicSharedMemorySize, FLASH_SMEM);

  const long long bt_v = (long long)BT * Vv;
  float* logits = ((long long)out_size >= bt_v) ? (float*)d_out : scratch;

  embed_kernel<<<BT * Ee / 4 / 256, 256>>>(idx, tok, pos);

  const size_t FAM = (size_t)Ll * Ee * Ee;
  dim3 tb(32, 8), tg(Ee/32, Ee/32, Ll);
  transpose_w<<<tg, tb>>>(Wq,    wt + 0*FAM);
  transpose_w<<<tg, tb>>>(Wk,    wt + 1*FAM);
  transpose_w<<<tg, tb>>>(Wv,    wt + 2*FAM);
  transpose_w<<<tg, tb>>>(projw, wt + 3*FAM);
  transpose_w<<<tg, tb>>>(fw1,   wt + 4*FAM);
  transpose_w<<<tg, tb>>>(fw2,   wt + 5*FAM);
  transpose_lm<<<dim3(Ee/32, NPAD/32), tb>>>(lmw, lmwt);

  dim3 gEE(BT / 128, Ee / 128);      // x = M blocks, y = N blocks
  dim3 gAttn(Tt / 64, Bb * Hh);
  const size_t WL = (size_t)Ee * Ee;
  for (int l = 0; l < Ll; l++){
    size_t wo = (size_t)l * WL, bo = (size_t)l * Ee;
    ln_kernel<<<BT, 256>>>(x, hh, ln1w + bo, ln1b + bo);
    sgemm_hc<false,false,true ><<<gEE, 256, SGEMM_SMEM>>>(hh, wt + 0*FAM + wo, nullptr, nullptr, qh, BT, Ee, Ee, Ee);
    sgemm_hc<false,false,true ><<<gEE, 256, SGEMM_SMEM>>>(hh, wt + 1*FAM + wo, nullptr, nullptr, kh, BT, Ee, Ee, Ee);
    sgemm_hc<false,false,true ><<<gEE, 256, SGEMM_SMEM>>>(hh, wt + 2*FAM + wo, nullptr, nullptr, vh, BT, Ee, Ee, Ee);
    flash_attn<<<gAttn, 128, FLASH_SMEM>>>(qh, kh, vh);
    sgemm_hc<false,true ,false><<<gEE, 256, SGEMM_SMEM>>>(oh,  wt + 3*FAM + wo, projb + bo, x, x, BT, Ee, Ee, Ee);
    ln_kernel<<<BT, 256>>>(x, hh, ln2w + bo, ln2b + bo);
    sgemm_hc<true ,false,true ><<<gEE, 256, SGEMM_SMEM>>>(hh,  wt + 4*FAM + wo, fb1 + bo, nullptr, ffh, BT, Ee, Ee, Ee);
    sgemm_hc<false,true ,false><<<gEE, 256, SGEMM_SMEM>>>(ffh, wt + 5*FAM + wo, fb2 + bo, x, x, BT, Ee, Ee, Ee);
  }

  ln_kernel<<<BT, 256>>>(x, hh, lnfw, lnfb);
  sgemm_hc<false,false,false><<<dim3(BT / 128, NPAD / 128), 256, SGEMM_SMEM>>>(
      hh, lmwt, lmb, nullptr, logits, BT, Vv, Ee, Ee);

  if ((long long)out_size != bt_v){
    loss_row<<<BT, 256>>>(logits, targets);
    float* lossptr = ((long long)out_size > bt_v) ? ((float*)d_out) + bt_v
                                                  : (float*)d_out;
    loss_final<<<1, 256>>>(lossptr);
  }
}

// round 9
// speedup vs baseline: 6.1679x; 1.0600x over previous
#include <cuda_runtime.h>
#include <cuda_fp16.h>
#include <math.h>
#include <stdint.h>

#define Bb 4
#define Tt 1024
#define Vv 50257
#define Ee 1024
#define Hh 16
#define Ll 8
#define Dd 64
#define BT (Bb*Tt)
#define NPAD 50304   // Vv padded to multiple of 128
#define QS  (3*Ee)   // packed qkv row stride

// ---------------- device scratch (static, allocation-free) ----------------
__device__ float  g_x [BT*Ee];                       // fp32 residual stream
__device__ __half g_hh[BT*Ee];                       // LN output (GEMM A)
__device__ __half g_qkvh[(size_t)BT * QS];           // packed q|k|v half
__device__ __half g_oh[BT*Ee];
__device__ __half g_ffh[BT*Ee];
__device__ __half g_wt[(size_t)3 * Ll * Ee * Ee];    // proj/fw1/fw2 transposed [N][K] half
__device__ __half g_wqkv[(size_t)Ll * 3 * Ee * Ee];  // per-layer [3E][E] transposed half
__device__ __half g_lmwt[(size_t)NPAD * Ee];         // LM head transposed [NPAD][Ee] half
__device__ float  g_rowloss[BT];
__device__ float  g_logits_scratch[205852672ull];    // fallback logits buffer

// ---------------- helpers ----------------
__device__ __forceinline__ uint32_t f2tf(float f){
  uint32_t u; asm("cvt.rna.tf32.f32 %0, %1;" : "=r"(u) : "f"(f)); return u;
}
__device__ __forceinline__ void mma8(float* c, const uint32_t* a, const uint32_t* b){
  asm volatile("mma.sync.aligned.m16n8k8.row.col.f32.tf32.tf32.f32 "
    "{%0,%1,%2,%3}, {%4,%5,%6,%7}, {%8,%9}, {%0,%1,%2,%3};"
    : "+f"(c[0]), "+f"(c[1]), "+f"(c[2]), "+f"(c[3])
    : "r"(a[0]), "r"(a[1]), "r"(a[2]), "r"(a[3]), "r"(b[0]), "r"(b[1]));
}
__device__ __forceinline__ void mma16(float* c, const uint32_t* a, const uint32_t* b){
  asm volatile("mma.sync.aligned.m16n8k16.row.col.f32.f16.f16.f32 "
    "{%0,%1,%2,%3}, {%4,%5,%6,%7}, {%8,%9}, {%0,%1,%2,%3};"
    : "+f"(c[0]), "+f"(c[1]), "+f"(c[2]), "+f"(c[3])
    : "r"(a[0]), "r"(a[1]), "r"(a[2]), "r"(a[3]), "r"(b[0]), "r"(b[1]));
}
__device__ __forceinline__ void ldsm_x4(uint32_t& r0, uint32_t& r1,
                                        uint32_t& r2, uint32_t& r3, uint32_t addr){
  asm volatile("ldmatrix.sync.aligned.m8n8.x4.shared.b16 {%0,%1,%2,%3}, [%4];"
    : "=r"(r0), "=r"(r1), "=r"(r2), "=r"(r3) : "r"(addr));
}
__device__ __forceinline__ void cp16(void* smem_ptr, const void* g){
  uint32_t s = (uint32_t)__cvta_generic_to_shared(smem_ptr);
  asm volatile("cp.async.cg.shared.global [%0], [%1], 16;" :: "r"(s), "l"(g));
}
__device__ __forceinline__ void cp_commit(){ asm volatile("cp.async.commit_group;"); }
template<int N> __device__ __forceinline__ void cp_wait(){
  asm volatile("cp.async.wait_group %0;" :: "n"(N));
}
__device__ __forceinline__ uint32_t smem_u32(const void* p){
  return (uint32_t)__cvta_generic_to_shared(p);
}

__device__ __forceinline__ float warpSum(float v){
  #pragma unroll
  for (int o = 16; o > 0; o >>= 1) v += __shfl_down_sync(0xffffffffu, v, o);
  return v;
}
__device__ __forceinline__ float warpMax(float v){
  #pragma unroll
  for (int o = 16; o > 0; o >>= 1) v = fmaxf(v, __shfl_down_sync(0xffffffffu, v, o));
  return v;
}
template<int OP>
__device__ __forceinline__ float blockReduce(float v){
  __shared__ float sh[33];
  int lane = threadIdx.x & 31, wid = threadIdx.x >> 5;
  v = OP ? warpMax(v) : warpSum(v);
  __syncthreads();
  if (lane == 0) sh[wid] = v;
  __syncthreads();
  int nw = blockDim.x >> 5;
  if (wid == 0){
    float u = (lane < nw) ? sh[lane] : (OP ? -INFINITY : 0.0f);
    u = OP ? warpMax(u) : warpSum(u);
    if (lane == 0) sh[32] = u;
  }
  __syncthreads();
  return sh[32];
}

// ---------------- embedding (fp32 residual) ----------------
__global__ void embed_kernel(const int* __restrict__ idx,
                             const float* __restrict__ tok,
                             const float* __restrict__ pos){
  int i  = blockIdx.x * 256 + threadIdx.x;
  int e4 = i & (Ee/4 - 1);
  int bt = i >> 8;
  int t  = bt & (Tt - 1);
  int token = idx[bt];
  float4 tv = ((const float4*)(tok + (size_t)token * Ee))[e4];
  float4 pv = ((const float4*)(pos + (size_t)t     * Ee))[e4];
  ((float4*)(g_x + (size_t)bt * Ee))[e4] =
      make_float4(tv.x*pv.x, tv.y*pv.y, tv.z*pv.z, tv.w*pv.w);
}

// ---------------- layernorm: fp32 in -> half out ----------------
__global__ void ln_kernel(const float* __restrict__ in, __half* __restrict__ out,
                          const float* __restrict__ w, const float* __restrict__ b){
  int row = blockIdx.x;
  float4 v = ((const float4*)(in + (size_t)row * Ee))[threadIdx.x];
  float mu = blockReduce<0>(v.x + v.y + v.z + v.w) * (1.0f / Ee);
  float dx = v.x - mu, dy = v.y - mu, dz = v.z - mu, dw = v.w - mu;
  float var = blockReduce<0>(dx*dx + dy*dy + dz*dz + dw*dw) * (1.0f / Ee);
  float rs = rsqrtf(var + 1e-5f);
  float4 wv = ((const float4*)w)[threadIdx.x];
  float4 bv = ((const float4*)b)[threadIdx.x];
  __half2* op = (__half2*)(out + (size_t)row * Ee) + threadIdx.x * 2;
  op[0] = __floats2half2_rn(dx*rs*wv.x + bv.x, dy*rs*wv.y + bv.y);
  op[1] = __floats2half2_rn(dz*rs*wv.z + bv.z, dw*rs*wv.w + bv.w);
}

// ---------------- weight transpose+half: src[K][N] f32 (per layer EE) -> dst[N][K] half
// dst layer stride given (EE for plain families, 3EE for packed qkv)
__global__ void transpose_w(const float* __restrict__ src, __half* __restrict__ dst,
                            size_t dstLayerStride){
  __shared__ float t[32][33];
  size_t sbase = (size_t)blockIdx.z * Ee * Ee;
  size_t dbase = (size_t)blockIdx.z * dstLayerStride;
  int k0 = blockIdx.x * 32, n0 = blockIdx.y * 32;
  int tx = threadIdx.x, ty = threadIdx.y;  // 32 x 8
  #pragma unroll
  for (int i = 0; i < 4; i++)
    t[ty + i*8][tx] = src[sbase + (size_t)(k0 + ty + i*8) * Ee + n0 + tx];
  __syncthreads();
  #pragma unroll
  for (int i = 0; i < 4; i++)
    dst[dbase + (size_t)(n0 + ty + i*8) * Ee + k0 + tx] = __float2half(t[tx][ty + i*8]);
}

// LM head: src[Ee][Vv] f32 -> dst[NPAD][Ee] half (zero-padded rows)
__global__ void transpose_lm(const float* __restrict__ src, __half* __restrict__ dst){
  __shared__ float t[32][33];
  int k0 = blockIdx.x * 32, n0 = blockIdx.y * 32;
  int tx = threadIdx.x, ty = threadIdx.y;
  #pragma unroll
  for (int i = 0; i < 4; i++){
    int n = n0 + tx;
    t[ty + i*8][tx] = (n < Vv) ? src[(size_t)(k0 + ty + i*8) * Vv + n] : 0.0f;
  }
  __syncthreads();
  #pragma unroll
  for (int i = 0; i < 4; i++)
    dst[(size_t)(n0 + ty + i*8) * Ee + k0 + tx] = __float2half(t[tx][ty + i*8]);
}

// ---------------- fp16 tensor-core GEMM, 3-stage cp.async + ldmatrix ----------------
// C[M,N] = act(A[M,K]@Bt[N,K]^T + bias)(+resid). BM=BN=128, BK=32, mma m16n8k16.
#define HPITCH 40                        // halfs per smem row (conflict-free for LDSM)
#define TILEH  (128*HPITCH)              // 5120 halfs per operand tile
#define STAGEH (2*TILEH)                 // 10240 halfs per stage
#define SGEMM_SMEM (3*STAGEH*2)          // 61440 bytes

template<bool RELU, bool RESID, bool OUTH>
__global__ __launch_bounds__(256, 2)
void sgemm_hc(const __half* __restrict__ A, const __half* __restrict__ Bt,
              const float* __restrict__ bias, const float* __restrict__ resid,
              void* __restrict__ C, int M, int N, int K, int Kb){
  extern __shared__ __align__(16) __half hsm[];
  int tid = threadIdx.x;
  int lane = tid & 31, warp = tid >> 5;
  int wm = warp >> 2, wn = warp & 3;
  int qk = lane & 3, qm = lane >> 2;
  int row0 = blockIdx.x * 128, col0 = blockIdx.y * 128;
  float acc[4][4][4] = {};

  // per-lane ldmatrix offsets (in half units)
  int j8 = lane >> 3, r8 = lane & 7;
  int a_off[4], b_off[2];
  #pragma unroll
  for (int mi = 0; mi < 4; mi++)
    a_off[mi] = (wm*64 + mi*16 + ((j8 & 1) << 3) + r8) * HPITCH + ((j8 >> 1) << 3);
  #pragma unroll
  for (int p = 0; p < 2; p++)
    b_off[p] = (wn*32 + (p*2 + (j8 >> 1))*8 + r8) * HPITCH + ((j8 & 1) << 3);

  auto prefetch = [&](int kt, int s){
    __half* As = hsm + s * STAGEH;
    __half* Bs = As + TILEH;
    #pragma unroll
    for (int l = 0; l < 2; l++){
      int f = tid + l * 256;                 // 512 chunks: 128 rows x 4 x 16B
      int r = f >> 2, c8 = (f & 3) << 3;
      cp16(As + r * HPITCH + c8, A  + (size_t)(row0 + r) * K  + kt + c8);
    }
    #pragma unroll
    for (int l = 0; l < 2; l++){
      int f = tid + l * 256;
      int r = f >> 2, c8 = (f & 3) << 3;
      cp16(Bs + r * HPITCH + c8, Bt + (size_t)(col0 + r) * Kb + kt + c8);
    }
  };

  int nk = K >> 5;
  prefetch(0, 0);  cp_commit();
  prefetch(32, 1); cp_commit();

  for (int t = 0; t < nk; t++){
    if (t < nk - 1) cp_wait<1>(); else cp_wait<0>();
    __syncthreads();     // publishes stage t%3; also orders reads of t-1 vs rewrite below
    uint32_t aU = smem_u32(hsm + (t % 3) * STAGEH);
    uint32_t bU = aU + TILEH * 2;
    #pragma unroll
    for (int ks = 0; ks < 2; ks++){
      int k0 = ks * 16;
      uint32_t af[4][4], bf[4][2];
      #pragma unroll
      for (int mi = 0; mi < 4; mi++)
        ldsm_x4(af[mi][0], af[mi][1], af[mi][2], af[mi][3],
                aU + (uint32_t)(a_off[mi] + k0) * 2);
      #pragma unroll
      for (int p = 0; p < 2; p++)
        ldsm_x4(bf[p*2][0], bf[p*2][1], bf[p*2+1][0], bf[p*2+1][1],
                bU + (uint32_t)(b_off[p] + k0) * 2);
      #pragma unroll
      for (int mi = 0; mi < 4; mi++)
        #pragma unroll
        for (int ni = 0; ni < 4; ni++)
          mma16(acc[mi][ni], af[mi], bf[ni]);
    }
    // no second barrier: prefetch targets stage (t+2)%3, untouched by iters t / t+1
    if (t + 2 < nk){ prefetch((t + 2) << 5, (t + 2) % 3); cp_commit(); }
  }

  #pragma unroll
  for (int mi = 0; mi < 4; mi++){
    int r = row0 + wm * 64 + mi * 16 + qm;
    #pragma unroll
    for (int ni = 0; ni < 4; ni++){
      int c = col0 + wn * 32 + ni * 8 + qk * 2;
      #pragma unroll
      for (int half_ = 0; half_ < 2; half_++){
        int rr = r + half_ * 8;
        float v0 = acc[mi][ni][half_ * 2 + 0];
        float v1 = acc[mi][ni][half_ * 2 + 1];
        if (bias){ if (c < N) v0 += bias[c]; if (c + 1 < N) v1 += bias[c + 1]; }
        if (RELU){ v0 = fmaxf(v0, 0.0f); v1 = fmaxf(v1, 0.0f); }
        if (RESID){
          const float* rp = resid + (size_t)rr * N;
          if (c < N) v0 += rp[c];
          if (c + 1 < N) v1 += rp[c + 1];
        }
        if (OUTH){
          __half* cp = (__half*)C + (size_t)rr * N;
          if (c + 1 < N) *(__half2*)(cp + c) = __floats2half2_rn(v0, v1);
          else if (c < N) cp[c] = __float2half(v0);
        } else {
          float* cp = (float*)C + (size_t)rr * N;
          if (((N & 1) == 0) && c + 1 < N) *(float2*)(cp + c) = make_float2(v0, v1);
          else {
            if (c     < N) cp[c    ] = v0;
            if (c + 1 < N) cp[c + 1] = v1;
          }
        }
      }
    }
  }
}

// ---------------- fused flash attention (causal, tf32 mma, packed-qkv half IO) ----------------
#define KPITCH 68
#define VPITCH 72
#define PPITCH 68
#define FLASH_SMEM ((64*KPITCH + 64*VPITCH + 64*PPITCH) * 4)   // 53248 B

__global__ __launch_bounds__(128)
void flash_attn(const __half* __restrict__ qkv){
  extern __shared__ __align__(16) float fsm[];
  float*    Ks  = fsm;
  float*    Vs  = fsm + 64 * KPITCH;
  float*    Ps  = Vs  + 64 * VPITCH;
  uint32_t* KsU = (uint32_t*)Ks;
  uint32_t* VsU = (uint32_t*)Vs;
  uint32_t* PsU = (uint32_t*)Ps;

  int it = blockIdx.x, bh = blockIdx.y;
  int b = bh >> 4, hd = bh & 15;
  const __half* qh = qkv + (size_t)b * Tt * QS + hd * Dd;            // q block
  const __half* kh = qh + Ee;                                        // k block
  const __half* vh = qh + 2 * Ee;                                    // v block

  int tid = threadIdx.x;
  int lane = tid & 31, warp = tid >> 5;
  int qk = lane & 3, qm = lane >> 2;
  int r0 = warp * 16;

  #pragma unroll
  for (int l = 0; l < 4; l++){
    int f = tid + l * 128;
    int r = f >> 3, c8 = (f & 7) << 3;
    uint4 u = *(const uint4*)(qh + (size_t)(it * 64 + r) * QS + c8);
    const __half2* hp = (const __half2*)&u;
    float* d = &Ps[r * PPITCH + c8];
    #pragma unroll
    for (int j = 0; j < 4; j++){
      float2 f2 = __half22float2(hp[j]);
      d[j*2] = f2.x; d[j*2+1] = f2.y;
    }
  }
  __syncthreads();
  uint32_t aq[8][4];
  #pragma unroll
  for (int ks = 0; ks < 8; ks++){
    aq[ks][0] = f2tf(Ps[(r0 + qm    ) * PPITCH + ks * 8 + qk]);
    aq[ks][1] = f2tf(Ps[(r0 + qm + 8) * PPITCH + ks * 8 + qk]);
    aq[ks][2] = f2tf(Ps[(r0 + qm    ) * PPITCH + ks * 8 + qk + 4]);
    aq[ks][3] = f2tf(Ps[(r0 + qm + 8) * PPITCH + ks * 8 + qk + 4]);
  }

  float oacc[8][4] = {};
  float mold[2] = {-INFINITY, -INFINITY};
  float lrun[2] = {0.0f, 0.0f};
  const float scale = 0.03125f;

  for (int jt = 0; jt <= it; jt++){
    __syncthreads();
    #pragma unroll
    for (int l = 0; l < 4; l++){
      int f = tid + l * 128;
      int r = f >> 3, c8 = (f & 7) << 3;
      uint4 uk = *(const uint4*)(kh + (size_t)(jt * 64 + r) * QS + c8);
      const __half2* hk = (const __half2*)&uk;
      uint32_t* kd = &KsU[r * KPITCH + c8];
      #pragma unroll
      for (int j = 0; j < 4; j++){
        float2 f2 = __half22float2(hk[j]);
        kd[j*2] = f2tf(f2.x); kd[j*2+1] = f2tf(f2.y);
      }
      uint4 uv = *(const uint4*)(vh + (size_t)(jt * 64 + r) * QS + c8);
      const __half2* hv = (const __half2*)&uv;
      uint32_t* vd = &VsU[r * VPITCH + c8];
      #pragma unroll
      for (int j = 0; j < 4; j++){
        float2 f2 = __half22float2(hv[j]);
        vd[j*2] = f2tf(f2.x); vd[j*2+1] = f2tf(f2.y);
      }
    }
    __syncthreads();

    float sacc[8][4] = {};
    #pragma unroll
    for (int ks = 0; ks < 8; ks++){
      #pragma unroll
      for (int ni = 0; ni < 8; ni++){
        uint32_t ub[2];
        ub[0] = KsU[(ni * 8 + qm) * KPITCH + ks * 8 + qk];
        ub[1] = KsU[(ni * 8 + qm) * KPITCH + ks * 8 + qk + 4];
        mma8(sacc[ni], aq[ks], ub);
      }
    }

    bool diag = (jt == it);
    #pragma unroll
    for (int ni = 0; ni < 8; ni++)
      #pragma unroll
      for (int e = 0; e < 4; e++){
        float sv = sacc[ni][e] * scale;
        if (diag){
          int rr = r0 + qm + ((e >> 1) << 3);
          int cc = ni * 8 + (qk << 1) + (e & 1);
          if (cc > rr) sv = -INFINITY;
        }
        sacc[ni][e] = sv;
      }

    #pragma unroll
    for (int h = 0; h < 2; h++){
      float mr = -INFINITY;
      #pragma unroll
      for (int ni = 0; ni < 8; ni++)
        mr = fmaxf(mr, fmaxf(sacc[ni][h * 2], sacc[ni][h * 2 + 1]));
      mr = fmaxf(mr, __shfl_xor_sync(0xffffffffu, mr, 1));
      mr = fmaxf(mr, __shfl_xor_sync(0xffffffffu, mr, 2));
      float mn = fmaxf(mold[h], mr);
      float alpha = __expf(mold[h] - mn);
      mold[h] = mn;
      float ls = 0.0f;
      int prow = (r0 + qm + h * 8) * PPITCH;
      #pragma unroll
      for (int ni = 0; ni < 8; ni++){
        float p0 = __expf(sacc[ni][h * 2    ] - mn);
        float p1 = __expf(sacc[ni][h * 2 + 1] - mn);
        ls += p0 + p1;
        PsU[prow + ni * 8 + qk * 2    ] = f2tf(p0);
        PsU[prow + ni * 8 + qk * 2 + 1] = f2tf(p1);
        oacc[ni][h * 2    ] *= alpha;
        oacc[ni][h * 2 + 1] *= alpha;
      }
      ls += __shfl_xor_sync(0xffffffffu, ls, 1);
      ls += __shfl_xor_sync(0xffffffffu, ls, 2);
      lrun[h] = lrun[h] * alpha + ls;
    }
    __syncwarp();

    #pragma unroll
    for (int ks = 0; ks < 8; ks++){
      uint32_t ua[4];
      ua[0] = PsU[(r0 + qm    ) * PPITCH + ks * 8 + qk];
      ua[1] = PsU[(r0 + qm + 8) * PPITCH + ks * 8 + qk];
      ua[2] = PsU[(r0 + qm    ) * PPITCH + ks * 8 + qk + 4];
      ua[3] = PsU[(r0 + qm + 8) * PPITCH + ks * 8 + qk + 4];
      #pragma unroll
      for (int ni = 0; ni < 8; ni++){
        uint32_t ub[2];
        ub[0] = VsU[(ks * 8 + qk    ) * VPITCH + ni * 8 + qm];
        ub[1] = VsU[(ks * 8 + qk + 4) * VPITCH + ni * 8 + qm];
        mma8(oacc[ni], ua, ub);
      }
    }
  }

  #pragma unroll
  for (int h = 0; h < 2; h++){
    float inv = 1.0f / lrun[h];
    int gi = it * 64 + r0 + qm + h * 8;
    __half* op = g_oh + (size_t)(b * Tt + gi) * Ee + hd * Dd;
    #pragma unroll
    for (int ni = 0; ni < 8; ni++)
      *(__half2*)(op + ni * 8 + qk * 2) =
          __floats2half2_rn(oacc[ni][h * 2] * inv, oacc[ni][h * 2 + 1] * inv);
  }
}

// ---------------- loss: single-pass online logsumexp ----------------
__global__ void loss_row(const float* __restrict__ logits, const int* __restrict__ tgt){
  int r = blockIdx.x;
  const float* lp = logits + (size_t)r * Vv;
  int tid = threadIdx.x, lane = tid & 31, wid = tid >> 5;
  float m = -INFINITY, s = 0.0f;
  for (int c = tid; c < Vv; c += 256){
    float v = lp[c];
    if (v > m){ s = s * __expf(m - v) + 1.0f; m = v; }
    else s += __expf(v - m);
  }
  #pragma unroll
  for (int o = 16; o > 0; o >>= 1){
    float mo = __shfl_down_sync(0xffffffffu, m, o);
    float so = __shfl_down_sync(0xffffffffu, s, o);
    float mn = fmaxf(m, mo);
    s = s * __expf(m - mn) + so * __expf(mo - mn);
    m = mn;
  }
  __shared__ float shm[8], shs[8];
  if (lane == 0){ shm[wid] = m; shs[wid] = s; }
  __syncthreads();
  if (tid == 0){
    float M = shm[0], S = shs[0];
    #pragma unroll
    for (int i = 1; i < 8; i++){
      float mn = fmaxf(M, shm[i]);
      S = S * __expf(M - mn) + shs[i] * __expf(shm[i] - mn);
      M = mn;
    }
    g_rowloss[r] = -(lp[tgt[r]] - M - logf(S));
  }
}
__global__ void loss_final(float* __restrict__ out){
  float s = 0.0f;
  for (int i = threadIdx.x; i < BT; i += 256) s += g_rowloss[i];
  s = blockReduce<0>(s);
  if (threadIdx.x == 0) out[0] = s / (float)BT;
}

// ---------------- launch ----------------
extern "C" void kernel_launch(void* const* d_in, const int* in_sizes, int n_in,
                              void* d_out, int out_size){
  const int*   idx     = (const int*)  d_in[0];
  const int*   targets = (const int*)  d_in[1];
  const float* tok     = (const float*)d_in[2];
  const float* pos     = (const float*)d_in[3];
  const float* ln1w    = (const float*)d_in[4];
  const float* ln1b    = (const float*)d_in[5];
  const float* Wq      = (const float*)d_in[6];
  const float* Wk      = (const float*)d_in[7];
  const float* Wv      = (const float*)d_in[8];
  const float* projw   = (const float*)d_in[9];
  const float* projb   = (const float*)d_in[10];
  const float* ln2w    = (const float*)d_in[11];
  const float* ln2b    = (const float*)d_in[12];
  const float* fw1     = (const float*)d_in[13];
  const float* fb1     = (const float*)d_in[14];
  const float* fw2     = (const float*)d_in[15];
  const float* fb2     = (const float*)d_in[16];
  const float* lnfw    = (const float*)d_in[17];
  const float* lnfb    = (const float*)d_in[18];
  const float* lmw     = (const float*)d_in[19];
  const float* lmb     = (const float*)d_in[20];

  float  *x, *scratch;
  __half *hh, *qkvh, *oh, *ffh, *wt, *wqkv, *lmwt;
  cudaGetSymbolAddress((void**)&x,    g_x);
  cudaGetSymbolAddress((void**)&hh,   g_hh);
  cudaGetSymbolAddress((void**)&qkvh, g_qkvh);
  cudaGetSymbolAddress((void**)&oh,   g_oh);
  cudaGetSymbolAddress((void**)&ffh,  g_ffh);
  cudaGetSymbolAddress((void**)&wt,   g_wt);
  cudaGetSymbolAddress((void**)&wqkv, g_wqkv);
  cudaGetSymbolAddress((void**)&lmwt, g_lmwt);
  cudaGetSymbolAddress((void**)&scratch, g_logits_scratch);

  cudaFuncSetAttribute(sgemm_hc<false,false,true >, cudaFuncAttributeMaxDynamicSharedMemorySize, SGEMM_SMEM);
  cudaFuncSetAttribute(sgemm_hc<false,true ,false>, cudaFuncAttributeMaxDynamicSharedMemorySize, SGEMM_SMEM);
  cudaFuncSetAttribute(sgemm_hc<true ,false,true >, cudaFuncAttributeMaxDynamicSharedMemorySize, SGEMM_SMEM);
  cudaFuncSetAttribute(sgemm_hc<false,false,false>, cudaFuncAttributeMaxDynamicSharedMemorySize, SGEMM_SMEM);
  cudaFuncSetAttribute(flash_attn, cudaFuncAttributeMaxDynamicSharedMemorySize, FLASH_SMEM);

  const long long bt_v = (long long)BT * Vv;
  float* logits = ((long long)out_size >= bt_v) ? (float*)d_out : scratch;

  embed_kernel<<<BT * Ee / 4 / 256, 256>>>(idx, tok, pos);

  const size_t EE  = (size_t)Ee * Ee;
  const size_t FAM = (size_t)Ll * EE;
  dim3 tb(32, 8), tg(Ee/32, Ee/32, Ll);
  // packed qkv: layer stride 3EE, family offset f*EE inside each layer
  transpose_w<<<tg, tb>>>(Wq,    wqkv + 0*EE, 3*EE);
  transpose_w<<<tg, tb>>>(Wk,    wqkv + 1*EE, 3*EE);
  transpose_w<<<tg, tb>>>(Wv,    wqkv + 2*EE, 3*EE);
  transpose_w<<<tg, tb>>>(projw, wt + 0*FAM, EE);
  transpose_w<<<tg, tb>>>(fw1,   wt + 1*FAM, EE);
  transpose_w<<<tg, tb>>>(fw2,   wt + 2*FAM, EE);
  transpose_lm<<<dim3(Ee/32, NPAD/32), tb>>>(lmw, lmwt);

  dim3 gEE (BT / 128, Ee / 128);        // (32, 8)
  dim3 gQKV(BT / 128, 3 * Ee / 128);    // (32, 24)
  dim3 gAttn(Tt / 64, Bb * Hh);
  for (int l = 0; l < Ll; l++){
    size_t wo = (size_t)l * EE, bo = (size_t)l * Ee;
    ln_kernel<<<BT, 256>>>(x, hh, ln1w + bo, ln1b + bo);
    sgemm_hc<false,false,true ><<<gQKV, 256, SGEMM_SMEM>>>(
        hh, wqkv + (size_t)l * 3 * EE, nullptr, nullptr, qkvh, BT, 3*Ee, Ee, Ee);
    flash_attn<<<gAttn, 128, FLASH_SMEM>>>(qkvh);
    sgemm_hc<false,true ,false><<<gEE, 256, SGEMM_SMEM>>>(oh,  wt + 0*FAM + wo, projb + bo, x, x, BT, Ee, Ee, Ee);
    ln_kernel<<<BT, 256>>>(x, hh, ln2w + bo, ln2b + bo);
    sgemm_hc<true ,false,true ><<<gEE, 256, SGEMM_SMEM>>>(hh,  wt + 1*FAM + wo, fb1 + bo, nullptr, ffh, BT, Ee, Ee, Ee);
    sgemm_hc<false,true ,false><<<gEE, 256, SGEMM_SMEM>>>(ffh, wt + 2*FAM + wo, fb2 + bo, x, x, BT, Ee, Ee, Ee);
  }

  ln_kernel<<<BT, 256>>>(x, hh, lnfw, lnfb);
  sgemm_hc<false,false,false><<<dim3(BT / 128, NPAD / 128), 256, SGEMM_SMEM>>>(
      hh, lmwt, lmb, nullptr, logits, BT, Vv, Ee, Ee);

  if ((long long)out_size != bt_v){
    loss_row<<<BT, 256>>>(logits, targets);
    float* lossptr = ((long long)out_size > bt_v) ? ((float*)d_out) + bt_v
                                                  : (float*)d_out;
    loss_final<<<1, 256>>>(lossptr);
  }
}

// round 10
// speedup vs baseline: 7.0954x; 1.1504x over previous
#include <cuda_runtime.h>
#include <cuda_fp16.h>
#include <math.h>
#include <stdint.h>

#define Bb 4
#define Tt 1024
#define Vv 50257
#define Ee 1024
#define Hh 16
#define Ll 8
#define Dd 64
#define BT (Bb*Tt)
#define NPAD 50304   // Vv padded to multiple of 128
#define QS  (3*Ee)   // packed qkv row stride

// ---------------- device scratch (static, allocation-free) ----------------
__device__ float  g_x [BT*Ee];                       // fp32 residual stream
__device__ __half g_hh[BT*Ee];                       // LN output (GEMM A)
__device__ __half g_qkvh[(size_t)BT * QS];           // packed q|k|v half
__device__ __half g_oh[BT*Ee];
__device__ __half g_ffh[BT*Ee];
__device__ __half g_wt[(size_t)3 * Ll * Ee * Ee];    // proj/fw1/fw2 transposed [N][K] half
__device__ __half g_wqkv[(size_t)Ll * 3 * Ee * Ee];  // per-layer [3E][E] transposed half
__device__ __half g_lmwt[(size_t)NPAD * Ee];         // LM head transposed [NPAD][Ee] half
__device__ float  g_rowloss[BT];
__device__ float  g_logits_scratch[205852672ull];    // fallback logits buffer

// ---------------- helpers ----------------
__device__ __forceinline__ void mma16(float* c, const uint32_t* a, const uint32_t* b){
  asm volatile("mma.sync.aligned.m16n8k16.row.col.f32.f16.f16.f32 "
    "{%0,%1,%2,%3}, {%4,%5,%6,%7}, {%8,%9}, {%0,%1,%2,%3};"
    : "+f"(c[0]), "+f"(c[1]), "+f"(c[2]), "+f"(c[3])
    : "r"(a[0]), "r"(a[1]), "r"(a[2]), "r"(a[3]), "r"(b[0]), "r"(b[1]));
}
__device__ __forceinline__ void ldsm_x4(uint32_t& r0, uint32_t& r1,
                                        uint32_t& r2, uint32_t& r3, uint32_t addr){
  asm volatile("ldmatrix.sync.aligned.m8n8.x4.shared.b16 {%0,%1,%2,%3}, [%4];"
    : "=r"(r0), "=r"(r1), "=r"(r2), "=r"(r3) : "r"(addr));
}
__device__ __forceinline__ void ldsm_x4_t(uint32_t& r0, uint32_t& r1,
                                          uint32_t& r2, uint32_t& r3, uint32_t addr){
  asm volatile("ldmatrix.sync.aligned.m8n8.x4.trans.shared.b16 {%0,%1,%2,%3}, [%4];"
    : "=r"(r0), "=r"(r1), "=r"(r2), "=r"(r3) : "r"(addr));
}
__device__ __forceinline__ void cp16(void* smem_ptr, const void* g){
  uint32_t s = (uint32_t)__cvta_generic_to_shared(smem_ptr);
  asm volatile("cp.async.cg.shared.global [%0], [%1], 16;" :: "r"(s), "l"(g));
}
__device__ __forceinline__ void cp_commit(){ asm volatile("cp.async.commit_group;"); }
template<int N> __device__ __forceinline__ void cp_wait(){
  asm volatile("cp.async.wait_group %0;" :: "n"(N));
}
__device__ __forceinline__ uint32_t smem_u32(const void* p){
  return (uint32_t)__cvta_generic_to_shared(p);
}

__device__ __forceinline__ float warpSum(float v){
  #pragma unroll
  for (int o = 16; o > 0; o >>= 1) v += __shfl_down_sync(0xffffffffu, v, o);
  return v;
}
__device__ __forceinline__ float warpMax(float v){
  #pragma unroll
  for (int o = 16; o > 0; o >>= 1) v = fmaxf(v, __shfl_down_sync(0xffffffffu, v, o));
  return v;
}
template<int OP>
__device__ __forceinline__ float blockReduce(float v){
  __shared__ float sh[33];
  int lane = threadIdx.x & 31, wid = threadIdx.x >> 5;
  v = OP ? warpMax(v) : warpSum(v);
  __syncthreads();
  if (lane == 0) sh[wid] = v;
  __syncthreads();
  int nw = blockDim.x >> 5;
  if (wid == 0){
    float u = (lane < nw) ? sh[lane] : (OP ? -INFINITY : 0.0f);
    u = OP ? warpMax(u) : warpSum(u);
    if (lane == 0) sh[32] = u;
  }
  __syncthreads();
  return sh[32];
}

// ---------------- embedding (fp32 residual) ----------------
__global__ void embed_kernel(const int* __restrict__ idx,
                             const float* __restrict__ tok,
                             const float* __restrict__ pos){
  int i  = blockIdx.x * 256 + threadIdx.x;
  int e4 = i & (Ee/4 - 1);
  int bt = i >> 8;
  int t  = bt & (Tt - 1);
  int token = idx[bt];
  float4 tv = ((const float4*)(tok + (size_t)token * Ee))[e4];
  float4 pv = ((const float4*)(pos + (size_t)t     * Ee))[e4];
  ((float4*)(g_x + (size_t)bt * Ee))[e4] =
      make_float4(tv.x*pv.x, tv.y*pv.y, tv.z*pv.z, tv.w*pv.w);
}

// ---------------- layernorm: fp32 in -> half out ----------------
__global__ void ln_kernel(const float* __restrict__ in, __half* __restrict__ out,
                          const float* __restrict__ w, const float* __restrict__ b){
  int row = blockIdx.x;
  float4 v = ((const float4*)(in + (size_t)row * Ee))[threadIdx.x];
  float mu = blockReduce<0>(v.x + v.y + v.z + v.w) * (1.0f / Ee);
  float dx = v.x - mu, dy = v.y - mu, dz = v.z - mu, dw = v.w - mu;
  float var = blockReduce<0>(dx*dx + dy*dy + dz*dz + dw*dw) * (1.0f / Ee);
  float rs = rsqrtf(var + 1e-5f);
  float4 wv = ((const float4*)w)[threadIdx.x];
  float4 bv = ((const float4*)b)[threadIdx.x];
  __half2* op = (__half2*)(out + (size_t)row * Ee) + threadIdx.x * 2;
  op[0] = __floats2half2_rn(dx*rs*wv.x + bv.x, dy*rs*wv.y + bv.y);
  op[1] = __floats2half2_rn(dz*rs*wv.z + bv.z, dw*rs*wv.w + bv.w);
}

// ---------------- weight transpose+half: src[K][N] f32 (per layer EE) -> dst[N][K] half
__global__ void transpose_w(const float* __restrict__ src, __half* __restrict__ dst,
                            size_t dstLayerStride){
  __shared__ float t[32][33];
  size_t sbase = (size_t)blockIdx.z * Ee * Ee;
  size_t dbase = (size_t)blockIdx.z * dstLayerStride;
  int k0 = blockIdx.x * 32, n0 = blockIdx.y * 32;
  int tx = threadIdx.x, ty = threadIdx.y;  // 32 x 8
  #pragma unroll
  for (int i = 0; i < 4; i++)
    t[ty + i*8][tx] = src[sbase + (size_t)(k0 + ty + i*8) * Ee + n0 + tx];
  __syncthreads();
  #pragma unroll
  for (int i = 0; i < 4; i++)
    dst[dbase + (size_t)(n0 + ty + i*8) * Ee + k0 + tx] = __float2half(t[tx][ty + i*8]);
}

// LM head: src[Ee][Vv] f32 -> dst[NPAD][Ee] half (zero-padded rows)
__global__ void transpose_lm(const float* __restrict__ src, __half* __restrict__ dst){
  __shared__ float t[32][33];
  int k0 = blockIdx.x * 32, n0 = blockIdx.y * 32;
  int tx = threadIdx.x, ty = threadIdx.y;
  #pragma unroll
  for (int i = 0; i < 4; i++){
    int n = n0 + tx;
    t[ty + i*8][tx] = (n < Vv) ? src[(size_t)(k0 + ty + i*8) * Vv + n] : 0.0f;
  }
  __syncthreads();
  #pragma unroll
  for (int i = 0; i < 4; i++)
    dst[(size_t)(n0 + ty + i*8) * Ee + k0 + tx] = __float2half(t[tx][ty + i*8]);
}

// ---------------- fp16 tensor-core GEMM, BK=64, 2-stage cp.async + ldmatrix ----------------
// C[M,N] = act(A[M,K]@Bt[N,K]^T + bias)(+resid). BM=BN=128, BK=64, mma m16n8k16.
#define HPITCH 72                        // halfs per smem row (36 words: 4r mod 32 distinct)
#define TILEH  (128*HPITCH)              // 9216 halfs per operand tile
#define STAGEH (2*TILEH)                 // 18432 halfs per stage
#define SGEMM_SMEM (2*STAGEH*2)          // 73728 bytes (2 stages)

template<bool RELU, bool RESID, bool OUTH>
__global__ __launch_bounds__(256, 2)
void sgemm_hc(const __half* __restrict__ A, const __half* __restrict__ Bt,
              const float* __restrict__ bias, const float* __restrict__ resid,
              void* __restrict__ C, int M, int N, int K, int Kb){
  extern __shared__ __align__(16) __half hsm[];
  int tid = threadIdx.x;
  int lane = tid & 31, warp = tid >> 5;
  int wm = warp >> 2, wn = warp & 3;
  int qk = lane & 3, qm = lane >> 2;
  int row0 = blockIdx.x * 128, col0 = blockIdx.y * 128;
  float acc[4][4][4] = {};

  // per-lane ldmatrix offsets (in half units)
  int j8 = lane >> 3, r8 = lane & 7;
  int a_off[4], b_off[2];
  #pragma unroll
  for (int mi = 0; mi < 4; mi++)
    a_off[mi] = (wm*64 + mi*16 + ((j8 & 1) << 3) + r8) * HPITCH + ((j8 >> 1) << 3);
  #pragma unroll
  for (int p = 0; p < 2; p++)
    b_off[p] = (wn*32 + (p*2 + (j8 >> 1))*8 + r8) * HPITCH + ((j8 & 1) << 3);

  auto prefetch = [&](int kt, int s){
    __half* As = hsm + s * STAGEH;
    __half* Bs = As + TILEH;
    #pragma unroll
    for (int l = 0; l < 4; l++){
      int f = tid + l * 256;                 // 1024 chunks: 128 rows x 8 x 16B
      int r = f >> 3, c8 = (f & 7) << 3;
      cp16(As + r * HPITCH + c8, A  + (size_t)(row0 + r) * K  + kt + c8);
    }
    #pragma unroll
    for (int l = 0; l < 4; l++){
      int f = tid + l * 256;
      int r = f >> 3, c8 = (f & 7) << 3;
      cp16(Bs + r * HPITCH + c8, Bt + (size_t)(col0 + r) * Kb + kt + c8);
    }
  };

  int nk = K >> 6;                            // 64-half K chunks
  prefetch(0, 0); cp_commit();

  for (int t = 0; t < nk; t++){
    cp_wait<0>();
    __syncthreads();     // publishes stage t&1; orders prior reads of (t+1)&1 vs prefetch
    if (t + 1 < nk){ prefetch((t + 1) << 6, (t + 1) & 1); cp_commit(); }
    uint32_t aU = smem_u32(hsm + (t & 1) * STAGEH);
    uint32_t bU = aU + TILEH * 2;
    #pragma unroll
    for (int ks = 0; ks < 4; ks++){
      int k0 = ks * 16;
      uint32_t af[4][4], bf[4][2];
      #pragma unroll
      for (int mi = 0; mi < 4; mi++)
        ldsm_x4(af[mi][0], af[mi][1], af[mi][2], af[mi][3],
                aU + (uint32_t)(a_off[mi] + k0) * 2);
      #pragma unroll
      for (int p = 0; p < 2; p++)
        ldsm_x4(bf[p*2][0], bf[p*2][1], bf[p*2+1][0], bf[p*2+1][1],
                bU + (uint32_t)(b_off[p] + k0) * 2);
      #pragma unroll
      for (int mi = 0; mi < 4; mi++)
        #pragma unroll
        for (int ni = 0; ni < 4; ni++)
          mma16(acc[mi][ni], af[mi], bf[ni]);
    }
  }

  #pragma unroll
  for (int mi = 0; mi < 4; mi++){
    int r = row0 + wm * 64 + mi * 16 + qm;
    #pragma unroll
    for (int ni = 0; ni < 4; ni++){
      int c = col0 + wn * 32 + ni * 8 + qk * 2;
      #pragma unroll
      for (int half_ = 0; half_ < 2; half_++){
        int rr = r + half_ * 8;
        float v0 = acc[mi][ni][half_ * 2 + 0];
        float v1 = acc[mi][ni][half_ * 2 + 1];
        if (bias){ if (c < N) v0 += bias[c]; if (c + 1 < N) v1 += bias[c + 1]; }
        if (RELU){ v0 = fmaxf(v0, 0.0f); v1 = fmaxf(v1, 0.0f); }
        if (RESID){
          const float* rp = resid + (size_t)rr * N;
          if (c < N) v0 += rp[c];
          if (c + 1 < N) v1 += rp[c + 1];
        }
        if (OUTH){
          __half* cp = (__half*)C + (size_t)rr * N;
          if (c + 1 < N) *(__half2*)(cp + c) = __floats2half2_rn(v0, v1);
          else if (c < N) cp[c] = __float2half(v0);
        } else {
          float* cp = (float*)C + (size_t)rr * N;
          if (((N & 1) == 0) && c + 1 < N) *(float2*)(cp + c) = make_float2(v0, v1);
          else {
            if (c     < N) cp[c    ] = v0;
            if (c + 1 < N) cp[c + 1] = v1;
          }
        }
      }
    }
  }
}

// ---------------- fused flash attention (causal, fp16 mma16, packed-qkv) ----------------
// grid (T/64, B*H), 128 threads = 4 warps; warp owns 16 q rows.
#define FPH 72                                       // half pitch for Ks/Vs/Ps
#define FLASH_SMEM (3 * 64 * FPH * 2)                // 27648 B

__global__ __launch_bounds__(128)
void flash_attn(const __half* __restrict__ qkv){
  extern __shared__ __align__(16) __half fsm[];
  __half* Ks = fsm;
  __half* Vs = fsm + 64 * FPH;
  __half* Ps = Vs  + 64 * FPH;
  uint32_t KsU = smem_u32(Ks), VsU = smem_u32(Vs), PsU = smem_u32(Ps);

  int it = blockIdx.x, bh = blockIdx.y;
  int b = bh >> 4, hd = bh & 15;
  const __half* qh = qkv + (size_t)b * Tt * QS + hd * Dd;
  const __half* kh = qh + Ee;
  const __half* vh = qh + 2 * Ee;

  int tid = threadIdx.x;
  int lane = tid & 31, warp = tid >> 5;
  int qk = lane & 3, qm = lane >> 2;
  int j8 = lane >> 3, r8 = lane & 7;
  int r0 = warp * 16;

  // ldmatrix lane offsets (half units)
  int aoff = (r0 + ((j8 & 1) << 3) + r8) * FPH + ((j8 >> 1) << 3);   // A m16 tile at warp rows
  int koff[4];
  #pragma unroll
  for (int p = 0; p < 4; p++)
    koff[p] = ((p*2 + (j8 >> 1))*8 + r8) * FPH + ((j8 & 1) << 3);    // K B-frags (8 n-blocks)
  int voff[4];
  #pragma unroll
  for (int p = 0; p < 4; p++)
    voff[p] = (((j8 & 1) << 3) + r8) * FPH + p*16 + ((j8 >> 1) << 3); // V trans B-frags

  // stage Q tile (64 rows x 64 halfs) into Ps, build per-warp A-frags
  #pragma unroll
  for (int l = 0; l < 4; l++){
    int f = tid + l * 128;
    int r = f >> 3, c8 = (f & 7) << 3;
    uint4 u = *(const uint4*)(qh + (size_t)(it * 64 + r) * QS + c8);
    *(uint4*)(Ps + r * FPH + c8) = u;
  }
  __syncthreads();
  uint32_t aq[4][4];
  #pragma unroll
  for (int ks = 0; ks < 4; ks++)
    ldsm_x4(aq[ks][0], aq[ks][1], aq[ks][2], aq[ks][3],
            PsU + (uint32_t)(aoff + ks * 16) * 2);

  float oacc[8][4] = {};
  float mold[2] = {-INFINITY, -INFINITY};
  float lrun[2] = {0.0f, 0.0f};
  const float scale = 0.03125f;   // E^{-1/2}

  for (int jt = 0; jt <= it; jt++){
    __syncthreads();              // Ks/Vs/Ps free (prev P@V reads done; iter0: aq built)
    #pragma unroll
    for (int l = 0; l < 4; l++){
      int f = tid + l * 128;
      int r = f >> 3, c8 = (f & 7) << 3;
      uint4 uk = *(const uint4*)(kh + (size_t)(jt * 64 + r) * QS + c8);
      *(uint4*)(Ks + r * FPH + c8) = uk;
      uint4 uv = *(const uint4*)(vh + (size_t)(jt * 64 + r) * QS + c8);
      *(uint4*)(Vs + r * FPH + c8) = uv;
    }
    __syncthreads();

    // S = Q @ K^T : warp's 16 rows x 64 keys
    float sacc[8][4] = {};
    #pragma unroll
    for (int ks = 0; ks < 4; ks++){
      int k0 = ks * 16;
      uint32_t bf[8][2];
      #pragma unroll
      for (int p = 0; p < 4; p++)
        ldsm_x4(bf[p*2][0], bf[p*2][1], bf[p*2+1][0], bf[p*2+1][1],
                KsU + (uint32_t)(koff[p] + k0) * 2);
      #pragma unroll
      for (int ni = 0; ni < 8; ni++)
        mma16(sacc[ni], aq[ks], bf[ni]);
    }

    // scale + causal mask (diagonal tile only)
    bool diag = (jt == it);
    #pragma unroll
    for (int ni = 0; ni < 8; ni++)
      #pragma unroll
      for (int e = 0; e < 4; e++){
        float sv = sacc[ni][e] * scale;
        if (diag){
          int rr = r0 + qm + ((e >> 1) << 3);
          int cc = ni * 8 + (qk << 1) + (e & 1);
          if (cc > rr) sv = -INFINITY;
        }
        sacc[ni][e] = sv;
      }

    // online softmax per row-half; P (half) -> warp's Ps rows
    #pragma unroll
    for (int h = 0; h < 2; h++){
      float mr = -INFINITY;
      #pragma unroll
      for (int ni = 0; ni < 8; ni++)
        mr = fmaxf(mr, fmaxf(sacc[ni][h * 2], sacc[ni][h * 2 + 1]));
      mr = fmaxf(mr, __shfl_xor_sync(0xffffffffu, mr, 1));
      mr = fmaxf(mr, __shfl_xor_sync(0xffffffffu, mr, 2));
      float mn = fmaxf(mold[h], mr);
      float alpha = __expf(mold[h] - mn);
      mold[h] = mn;
      float ls = 0.0f;
      __half* prow = Ps + (r0 + qm + h * 8) * FPH;
      #pragma unroll
      for (int ni = 0; ni < 8; ni++){
        float p0 = __expf(sacc[ni][h * 2    ] - mn);
        float p1 = __expf(sacc[ni][h * 2 + 1] - mn);
        ls += p0 + p1;
        *(__half2*)(prow + ni * 8 + qk * 2) = __floats2half2_rn(p0, p1);
        oacc[ni][h * 2    ] *= alpha;
        oacc[ni][h * 2 + 1] *= alpha;
      }
      ls += __shfl_xor_sync(0xffffffffu, ls, 1);
      ls += __shfl_xor_sync(0xffffffffu, ls, 2);
      lrun[h] = lrun[h] * alpha + ls;
    }
    __syncwarp();

    // O += P @ V  (A = P rows via ldsm; B = V via trans ldsm)
    #pragma unroll
    for (int ks = 0; ks < 4; ks++){
      int k0 = ks * 16;
      uint32_t ua[4];
      ldsm_x4(ua[0], ua[1], ua[2], ua[3], PsU + (uint32_t)(aoff + k0) * 2);
      uint32_t bf[8][2];
      #pragma unroll
      for (int p = 0; p < 4; p++)
        ldsm_x4_t(bf[p*2][0], bf[p*2][1], bf[p*2+1][0], bf[p*2+1][1],
                  VsU + (uint32_t)(voff[p] + k0 * FPH) * 2);
      #pragma unroll
      for (int ni = 0; ni < 8; ni++)
        mma16(oacc[ni], ua, bf[ni]);
    }
  }

  #pragma unroll
  for (int h = 0; h < 2; h++){
    float inv = 1.0f / lrun[h];
    int gi = it * 64 + r0 + qm + h * 8;
    __half* op = g_oh + (size_t)(b * Tt + gi) * Ee + hd * Dd;
    #pragma unroll
    for (int ni = 0; ni < 8; ni++)
      *(__half2*)(op + ni * 8 + qk * 2) =
          __floats2half2_rn(oacc[ni][h * 2] * inv, oacc[ni][h * 2 + 1] * inv);
  }
}

// ---------------- loss: single-pass online logsumexp ----------------
__global__ void loss_row(const float* __restrict__ logits, const int* __restrict__ tgt){
  int r = blockIdx.x;
  const float* lp = logits + (size_t)r * Vv;
  int tid = threadIdx.x, lane = tid & 31, wid = tid >> 5;
  float m = -INFINITY, s = 0.0f;
  for (int c = tid; c < Vv; c += 256){
    float v = lp[c];
    if (v > m){ s = s * __expf(m - v) + 1.0f; m = v; }
    else s += __expf(v - m);
  }
  #pragma unroll
  for (int o = 16; o > 0; o >>= 1){
    float mo = __shfl_down_sync(0xffffffffu, m, o);
    float so = __shfl_down_sync(0xffffffffu, s, o);
    float mn = fmaxf(m, mo);
    s = s * __expf(m - mn) + so * __expf(mo - mn);
    m = mn;
  }
  __shared__ float shm[8], shs[8];
  if (lane == 0){ shm[wid] = m; shs[wid] = s; }
  __syncthreads();
  if (tid == 0){
    float M = shm[0], S = shs[0];
    #pragma unroll
    for (int i = 1; i < 8; i++){
      float mn = fmaxf(M, shm[i]);
      S = S * __expf(M - mn) + shs[i] * __expf(shm[i] - mn);
      M = mn;
    }
    g_rowloss[r] = -(lp[tgt[r]] - M - logf(S));
  }
}
__global__ void loss_final(float* __restrict__ out){
  float s = 0.0f;
  for (int i = threadIdx.x; i < BT; i += 256) s += g_rowloss[i];
  s = blockReduce<0>(s);
  if (threadIdx.x == 0) out[0] = s / (float)BT;
}

// ---------------- launch ----------------
extern "C" void kernel_launch(void* const* d_in, const int* in_sizes, int n_in,
                              void* d_out, int out_size){
  const int*   idx     = (const int*)  d_in[0];
  const int*   targets = (const int*)  d_in[1];
  const float* tok     = (const float*)d_in[2];
  const float* pos     = (const float*)d_in[3];
  const float* ln1w    = (const float*)d_in[4];
  const float* ln1b    = (const float*)d_in[5];
  const float* Wq      = (const float*)d_in[6];
  const float* Wk      = (const float*)d_in[7];
  const float* Wv      = (const float*)d_in[8];
  const float* projw   = (const float*)d_in[9];
  const float* projb   = (const float*)d_in[10];
  const float* ln2w    = (const float*)d_in[11];
  const float* ln2b    = (const float*)d_in[12];
  const float* fw1     = (const float*)d_in[13];
  const float* fb1     = (const float*)d_in[14];
  const float* fw2     = (const float*)d_in[15];
  const float* fb2     = (const float*)d_in[16];
  const float* lnfw    = (const float*)d_in[17];
  const float* lnfb    = (const float*)d_in[18];
  const float* lmw     = (const float*)d_in[19];
  const float* lmb     = (const float*)d_in[20];

  float  *x, *scratch;
  __half *hh, *qkvh, *oh, *ffh, *wt, *wqkv, *lmwt;
  cudaGetSymbolAddress((void**)&x,    g_x);
  cudaGetSymbolAddress((void**)&hh,   g_hh);
  cudaGetSymbolAddress((void**)&qkvh, g_qkvh);
  cudaGetSymbolAddress((void**)&oh,   g_oh);
  cudaGetSymbolAddress((void**)&ffh,  g_ffh);
  cudaGetSymbolAddress((void**)&wt,   g_wt);
  cudaGetSymbolAddress((void**)&wqkv, g_wqkv);
  cudaGetSymbolAddress((void**)&lmwt, g_lmwt);
  cudaGetSymbolAddress((void**)&scratch, g_logits_scratch);

  cudaFuncSetAttribute(sgemm_hc<false,false,true >, cudaFuncAttributeMaxDynamicSharedMemorySize, SGEMM_SMEM);
  cudaFuncSetAttribute(sgemm_hc<false,true ,false>, cudaFuncAttributeMaxDynamicSharedMemorySize, SGEMM_SMEM);
  cudaFuncSetAttribute(sgemm_hc<true ,false,true >, cudaFuncAttributeMaxDynamicSharedMemorySize, SGEMM_SMEM);
  cudaFuncSetAttribute(sgemm_hc<false,false,false>, cudaFuncAttributeMaxDynamicSharedMemorySize, SGEMM_SMEM);
  cudaFuncSetAttribute(flash_attn, cudaFuncAttributeMaxDynamicSharedMemorySize, FLASH_SMEM);

  const long long bt_v = (long long)BT * Vv;
  float* logits = ((long long)out_size >= bt_v) ? (float*)d_out : scratch;

  embed_kernel<<<BT * Ee / 4 / 256, 256>>>(idx, tok, pos);

  const size_t EE  = (size_t)Ee * Ee;
  const size_t FAM = (size_t)Ll * EE;
  dim3 tb(32, 8), tg(Ee/32, Ee/32, Ll);
  transpose_w<<<tg, tb>>>(Wq,    wqkv + 0*EE, 3*EE);
  transpose_w<<<tg, tb>>>(Wk,    wqkv + 1*EE, 3*EE);
  transpose_w<<<tg, tb>>>(Wv,    wqkv + 2*EE, 3*EE);
  transpose_w<<<tg, tb>>>(projw, wt + 0*FAM, EE);
  transpose_w<<<tg, tb>>>(fw1,   wt + 1*FAM, EE);
  transpose_w<<<tg, tb>>>(fw2,   wt + 2*FAM, EE);
  transpose_lm<<<dim3(Ee/32, NPAD/32), tb>>>(lmw, lmwt);

  dim3 gEE (BT / 128, Ee / 128);        // (32, 8)
  dim3 gQKV(BT / 128, 3 * Ee / 128);    // (32, 24)
  dim3 gAttn(Tt / 64, Bb * Hh);
  for (int l = 0; l < Ll; l++){
    size_t wo = (size_t)l * EE, bo = (size_t)l * Ee;
    ln_kernel<<<BT, 256>>>(x, hh, ln1w + bo, ln1b + bo);
    sgemm_hc<false,false,true ><<<gQKV, 256, SGEMM_SMEM>>>(
        hh, wqkv + (size_t)l * 3 * EE, nullptr, nullptr, qkvh, BT, 3*Ee, Ee, Ee);
    flash_attn<<<gAttn, 128, FLASH_SMEM>>>(qkvh);
    sgemm_hc<false,true ,false><<<gEE, 256, SGEMM_SMEM>>>(oh,  wt + 0*FAM + wo, projb + bo, x, x, BT, Ee, Ee, Ee);
    ln_kernel<<<BT, 256>>>(x, hh, ln2w + bo, ln2b + bo);
    sgemm_hc<true ,false,true ><<<gEE, 256, SGEMM_SMEM>>>(hh,  wt + 1*FAM + wo, fb1 + bo, nullptr, ffh, BT, Ee, Ee, Ee);
    sgemm_hc<false,true ,false><<<gEE, 256, SGEMM_SMEM>>>(ffh, wt + 2*FAM + wo, fb2 + bo, x, x, BT, Ee, Ee, Ee);
  }

  ln_kernel<<<BT, 256>>>(x, hh, lnfw, lnfb);
  sgemm_hc<false,false,false><<<dim3(BT / 128, NPAD / 128), 256, SGEMM_SMEM>>>(
      hh, lmwt, lmb, nullptr, logits, BT, Vv, Ee, Ee);

  if ((long long)out_size != bt_v){
    loss_row<<<BT, 256>>>(logits, targets);
    float* lossptr = ((long long)out_size > bt_v) ? ((float*)d_out) + bt_v
                                                  : (float*)d_out;
    loss_final<<<1, 256>>>(lossptr);
  }
}